// round 6
// baseline (speedup 1.0000x reference)
#include <cuda_runtime.h>
#include <cuda_bf16.h>
#include <math.h>
#include <stdint.h>

#define NNODES 50000
#define MPAD   50048      // 391 * 128
#define KD     256
#define HEADS  4
#define EMAX   1700000

// ---------------- device scratch --------------------------------------------
__device__ float          g_hs[MPAD * KD];      // source transform (fp32)
__device__ __nv_bfloat16  g_Ahi[MPAD * KD];     // activation split hi
__device__ __nv_bfloat16  g_Alo[MPAD * KD];     // activation split lo
__device__ __nv_bfloat16  g_Bthi[3 * KD * KD];  // W^T split hi, all layers
__device__ __nv_bfloat16  g_Btlo[3 * KD * KD];  // W^T split lo, all layers
__device__ float          g_as[MPAD * HEADS];
__device__ float          g_ad[NNODES * HEADS];
__device__ float          g_vd[3 * KD * HEADS]; // Wd_l @ att_d_l, [l][k][h]
__device__ int            g_deg[NNODES];
__device__ int            g_rowptr[NNODES + 1];
__device__ int            g_cursor[NNODES];
__device__ int            g_srcs[EMAX];         // CSR-ordered SOURCE ids

// ---------------- helpers ----------------------------------------------------
__device__ __forceinline__ void split_pair(float a, float b, unsigned& hi, unsigned& lo) {
    __nv_bfloat16 ha = __float2bfloat16(a), hb = __float2bfloat16(b);
    float ra = a - __bfloat162float(ha);
    float rb = b - __bfloat162float(hb);
    __nv_bfloat162 h2 = __halves2bfloat162(ha, hb);
    __nv_bfloat162 l2 = __floats2bfloat162_rn(ra, rb);
    hi = *reinterpret_cast<unsigned*>(&h2);
    lo = *reinterpret_cast<unsigned*>(&l2);
}

__device__ __forceinline__ void mma_bf16(float* c, const uint32_t* a, const uint32_t* b) {
    asm volatile(
        "mma.sync.aligned.m16n8k16.row.col.f32.bf16.bf16.f32 "
        "{%0,%1,%2,%3},{%4,%5,%6,%7},{%8,%9},{%0,%1,%2,%3};"
        : "+f"(c[0]), "+f"(c[1]), "+f"(c[2]), "+f"(c[3])
        : "r"(a[0]), "r"(a[1]), "r"(a[2]), "r"(a[3]), "r"(b[0]), "r"(b[1]));
}

#define CP_ASYNC16(dst_u32, src_ptr) \
    asm volatile("cp.async.cg.shared.global [%0], [%1], 16;" \
                 :: "r"(dst_u32), "l"(src_ptr))
#define CP_COMMIT() asm volatile("cp.async.commit_group;" ::: "memory")
#define CP_WAIT0()  asm volatile("cp.async.wait_group 0;" ::: "memory")

// ---------------- CSR build --------------------------------------------------
__global__ void clear_deg_kernel() {
    int i = blockIdx.x * blockDim.x + threadIdx.x;
    if (i < NNODES) g_deg[i] = 0;
}
__global__ void count_deg_kernel(const int* __restrict__ dst, int e2) {
    int e = blockIdx.x * blockDim.x + threadIdx.x;
    if (e < e2) atomicAdd(&g_deg[dst[e]], 1);
}
__global__ void scan_kernel() {
    __shared__ int s[1024];
    int t = threadIdx.x;
    const int per = (NNODES + 1023) / 1024;
    int start = t * per;
    int end = start + per; if (end > NNODES) end = NNODES;
    int sum = 0;
    for (int i = start; i < end; i++) sum += g_deg[i];
    s[t] = sum;
    __syncthreads();
    for (int off = 1; off < 1024; off <<= 1) {
        int v = (t >= off) ? s[t - off] : 0;
        __syncthreads();
        s[t] += v;
        __syncthreads();
    }
    int run = (t > 0) ? s[t - 1] : 0;
    for (int i = start; i < end; i++) {
        int d = g_deg[i];
        g_rowptr[i] = run;
        g_cursor[i] = run;
        run += d;
    }
    if (t == 0) g_rowptr[NNODES] = s[1023];
}
__global__ void scatter_kernel(const int* __restrict__ src,
                               const int* __restrict__ dst, int e2) {
    int e = blockIdx.x * blockDim.x + threadIdx.x;
    if (e < e2) {
        int pos = atomicAdd(&g_cursor[dst[e]], 1);
        g_srcs[pos] = src[e];
    }
}

// ---------------- layer-0 pre-split: x -> bf16 hi/lo -------------------------
__global__ void split_x_kernel(const float* __restrict__ A, int nf4) {
    int i = blockIdx.x * blockDim.x + threadIdx.x;
    if (i >= nf4) return;
    float4 v = ((const float4*)A)[i];
    uint2 h, l;
    split_pair(v.x, v.y, h.x, l.x);
    split_pair(v.z, v.w, h.y, l.y);
    ((uint2*)g_Ahi)[i] = h;
    ((uint2*)g_Alo)[i] = l;
}

// ---------------- B transpose+split, all 3 layers ----------------------------
__global__ void btsplit_all_kernel(const float* __restrict__ W0,
                                   const float* __restrict__ W1,
                                   const float* __restrict__ W2) {
    int l = blockIdx.y;
    const float* W = (l == 0) ? W0 : (l == 1) ? W1 : W2;
    int i = blockIdx.x * blockDim.x + threadIdx.x;
    int n = i >> 8, k = i & 255;
    float v = W[k * KD + n];
    __nv_bfloat16 h = __float2bfloat16(v);
    g_Bthi[l * KD * KD + i] = h;
    g_Btlo[l * KD * KD + i] = __float2bfloat16(v - __bfloat162float(h));
}

// ---------------- vd[l][k][h] = sum_c Wd_l[k, h*64+c] * ad_l[h*64+c] ---------
__global__ void compute_vd_kernel(const float* __restrict__ Wd,
                                  const float* __restrict__ ad, int loff) {
    int idx = threadIdx.x;
    int k = idx >> 2;
    int h = idx & 3;
    float s = 0.f;
#pragma unroll 8
    for (int c = 0; c < 64; c++) s += Wd[k * KD + h * 64 + c] * ad[h * 64 + c];
    g_vd[loff + k * 4 + h] = s;
}

// ---------------- layer-0 a_d = x . vd0  (warp per node) ---------------------
__global__ void __launch_bounds__(256) ad0_kernel(const float* __restrict__ X) {
    __shared__ float svd[KD * 4];
    int tid = threadIdx.x;
    for (int i = tid; i < KD * 4; i += 256) svd[i] = g_vd[i];
    __syncthreads();
    int warp = tid >> 5, lane = tid & 31;
    int n = blockIdx.x * 8 + warp;
    if (n >= NNODES) return;
    const float4* x4 = (const float4*)X + (long)n * 64;
    float a0 = 0.f, a1 = 0.f, a2 = 0.f, a3 = 0.f;
#pragma unroll
    for (int g4 = 0; g4 < 2; g4++) {
        float4 xv = x4[lane * 2 + g4];
        const float* p = &svd[(lane * 8 + g4 * 4) * 4];
        a0 += xv.x * p[0] + xv.y * p[4] + xv.z * p[8]  + xv.w * p[12];
        a1 += xv.x * p[1] + xv.y * p[5] + xv.z * p[9]  + xv.w * p[13];
        a2 += xv.x * p[2] + xv.y * p[6] + xv.z * p[10] + xv.w * p[14];
        a3 += xv.x * p[3] + xv.y * p[7] + xv.z * p[11] + xv.w * p[15];
    }
#pragma unroll
    for (int off = 16; off > 0; off >>= 1) {
        a0 += __shfl_xor_sync(0xffffffffu, a0, off);
        a1 += __shfl_xor_sync(0xffffffffu, a1, off);
        a2 += __shfl_xor_sync(0xffffffffu, a2, off);
        a3 += __shfl_xor_sync(0xffffffffu, a3, off);
    }
    if (lane == 0) ((float4*)g_ad)[n] = make_float4(a0, a1, a2, a3);
}

// ---------------- GEMM: g_hs = A @ W_l, cp.async 2-stage, fused a_s ----------
#define S32 20
#define STAGE_W 10240
__global__ void __launch_bounds__(256) gemm_mma_kernel(const float* __restrict__ attS,
                                                       const __nv_bfloat16* __restrict__ Bh,
                                                       const __nv_bfloat16* __restrict__ Bl) {
    extern __shared__ uint32_t smem_u[];
    __shared__ float s_as[128][2];
    const int tid = threadIdx.x;
    const int wid = tid >> 5, lane = tid & 31;
    const int wm = wid >> 2, wn = wid & 3;
    const int row0 = blockIdx.x * 128;
    const int n0 = blockIdx.y * 128;
    const int g8 = lane >> 2, tq = lane & 3;
    const uint32_t smem_b = (uint32_t)__cvta_generic_to_shared(smem_u);

    ((float*)s_as)[tid] = 0.f;

    const int lr0 = tid >> 2;
    const int lc4 = tid & 3;
    float c[4][4][4];
#pragma unroll
    for (int mt = 0; mt < 4; mt++)
#pragma unroll
        for (int nt = 0; nt < 4; nt++)
#pragma unroll
            for (int j = 0; j < 4; j++) c[mt][nt][j] = 0.f;

#define LOAD_CHUNK(stg, cc) do {                                               \
    int k0 = (cc) * 32;                                                        \
    _Pragma("unroll")                                                          \
    for (int i = 0; i < 2; i++) {                                              \
        int r = lr0 + i * 64;                                                  \
        long ga = (long)(row0 + r) * KD + k0 + lc4 * 8;                        \
        long gb = (long)(n0 + r) * KD + k0 + lc4 * 8;                          \
        uint32_t so = smem_b + ((stg) * STAGE_W + r * S32 + lc4 * 4) * 4;      \
        CP_ASYNC16(so,            g_Ahi + ga);                                 \
        CP_ASYNC16(so + 2560 * 4, g_Alo + ga);                                 \
        CP_ASYNC16(so + 5120 * 4, Bh + gb);                                    \
        CP_ASYNC16(so + 7680 * 4, Bl + gb);                                    \
    }                                                                          \
} while (0)

    LOAD_CHUNK(0, 0);
    CP_COMMIT();

    for (int cch = 0; cch < 8; cch++) {
        const int stg = cch & 1;
        CP_WAIT0();
        __syncthreads();
        if (cch < 7) { LOAD_CHUNK(stg ^ 1, cch + 1); CP_COMMIT(); }
        const uint32_t* sAh = smem_u + stg * STAGE_W;
        const uint32_t* sAl = sAh + 2560;
        const uint32_t* sBh = sAh + 5120;
        const uint32_t* sBl = sAh + 7680;
#pragma unroll
        for (int kk = 0; kk < 2; kk++) {
            const int kb = kk * 8;
            uint32_t ah[4][4], al[4][4], bh[4][2], bl[4][2];
#pragma unroll
            for (int mt = 0; mt < 4; mt++) {
                int r = (wm * 64 + mt * 16 + g8) * S32 + kb + tq;
                int r8 = r + 8 * S32;
                ah[mt][0] = sAh[r];     ah[mt][1] = sAh[r8];
                ah[mt][2] = sAh[r + 4]; ah[mt][3] = sAh[r8 + 4];
                al[mt][0] = sAl[r];     al[mt][1] = sAl[r8];
                al[mt][2] = sAl[r + 4]; al[mt][3] = sAl[r8 + 4];
            }
#pragma unroll
            for (int nt = 0; nt < 4; nt++) {
                int r = (wn * 32 + nt * 8 + g8) * S32 + kb + tq;
                bh[nt][0] = sBh[r]; bh[nt][1] = sBh[r + 4];
                bl[nt][0] = sBl[r]; bl[nt][1] = sBl[r + 4];
            }
#pragma unroll
            for (int mt = 0; mt < 4; mt++)
#pragma unroll
                for (int nt = 0; nt < 4; nt++) {
                    mma_bf16(c[mt][nt], ah[mt], bh[nt]);
                    mma_bf16(c[mt][nt], ah[mt], bl[nt]);
                    mma_bf16(c[mt][nt], al[mt], bh[nt]);
                }
        }
        __syncthreads();
    }

#pragma unroll
    for (int mt = 0; mt < 4; mt++) {
        int r = row0 + wm * 64 + mt * 16 + g8;
#pragma unroll
        for (int nt = 0; nt < 4; nt++) {
            int col = n0 + wn * 32 + nt * 8 + tq * 2;
            *(float2*)&g_hs[(long)r * KD + col] = make_float2(c[mt][nt][0], c[mt][nt][1]);
            *(float2*)&g_hs[(long)(r + 8) * KD + col] = make_float2(c[mt][nt][2], c[mt][nt][3]);
        }
    }
    {
        float p0[4] = {0.f, 0.f, 0.f, 0.f};
        float p1[4] = {0.f, 0.f, 0.f, 0.f};
#pragma unroll
        for (int nt = 0; nt < 4; nt++) {
            int col = n0 + wn * 32 + nt * 8 + tq * 2;
            float a0 = attS[col], a1 = attS[col + 1];
#pragma unroll
            for (int mt = 0; mt < 4; mt++) {
                p0[mt] += c[mt][nt][0] * a0 + c[mt][nt][1] * a1;
                p1[mt] += c[mt][nt][2] * a0 + c[mt][nt][3] * a1;
            }
        }
        int hl = wn >> 1;
#pragma unroll
        for (int mt = 0; mt < 4; mt++) {
            p0[mt] += __shfl_xor_sync(0xffffffffu, p0[mt], 1);
            p0[mt] += __shfl_xor_sync(0xffffffffu, p0[mt], 2);
            p1[mt] += __shfl_xor_sync(0xffffffffu, p1[mt], 1);
            p1[mt] += __shfl_xor_sync(0xffffffffu, p1[mt], 2);
            if (tq == 0) {
                int rl = wm * 64 + mt * 16 + g8;
                atomicAdd(&s_as[rl][hl], p0[mt]);
                atomicAdd(&s_as[rl + 8][hl], p1[mt]);
            }
        }
        __syncthreads();
        int rl = tid >> 1, h2 = tid & 1;
        g_as[(row0 + rl) * 4 + blockIdx.y * 2 + h2] = s_as[rl][h2];
    }
}

// ---------------- aggregation: 2 nodes/block, 64 thr/node, float4 gather -----
// Warp pair per node: warp wp owns cols [wp*128, wp*128+128) (heads 2wp, 2wp+1).
// mode 0: elu(acc/den + bias) -> Ahi/Alo split; a_d(next) via vdn
// mode 1: head-mean + b2 + log_softmax -> out[n,64]
__global__ void __launch_bounds__(128) aggregate_kernel(const float* __restrict__ bias,
                                                        const float* __restrict__ vdn,
                                                        float* __restrict__ out,
                                                        int mode) {
    __shared__ float4 stage[4][32];
    __shared__ int    stsrc[4][32];
    __shared__ float  s_adp[2][2][4];
    __shared__ float  sh[2][64];
    __shared__ float  s_red[2][2];

    const int tid = threadIdx.x;
    const int w = tid >> 5, lane = tid & 31;
    const int ni = w >> 1;              // node within block (0/1)
    const int wp = w & 1;               // warp-pair index within node
    const int n = blockIdx.x * 2 + ni;

    if (mode == 1) {                    // zero head-mean accumulator
        sh[tid >> 6][tid & 63] = 0.f;
        __syncthreads();
    }

    const int base = g_rowptr[n];
    const int deg = g_rowptr[n + 1] - base;
    const float4 ad4 = ((const float4*)g_ad)[n];
    const float4* __restrict__ hs4 = (const float4*)g_hs;
    const int colIdx = wp * 32 + lane;  // float4 index within row (0..63)
    const int hsel = lane & 16;         // 0 -> first head of pair, else second

    float4 acc = make_float4(0.f, 0.f, 0.f, 0.f);
    float exsA = 0.f, exsB = 0.f;       // this warp's two heads
    for (int cs = 0; cs < deg; cs += 32) {
        int m = deg - cs; if (m > 32) m = 32;
        if (lane < m) {
            int sI = g_srcs[base + cs + lane];
            float4 a = ((const float4*)g_as)[sI];
            float v; float4 ex;
            v = a.x + ad4.x; v = v > 0.f ? v : 0.2f * v; ex.x = __expf(v);
            v = a.y + ad4.y; v = v > 0.f ? v : 0.2f * v; ex.y = __expf(v);
            v = a.z + ad4.z; v = v > 0.f ? v : 0.2f * v; ex.z = __expf(v);
            v = a.w + ad4.w; v = v > 0.f ? v : 0.2f * v; ex.w = __expf(v);
            stage[w][lane] = ex;
            stsrc[w][lane] = sI;
            exsA += wp ? ex.z : ex.x;
            exsB += wp ? ex.w : ex.y;
        }
        __syncwarp();
#pragma unroll 4
        for (int j = 0; j < m; j++) {
            float4 st = stage[w][j];
            int s = stsrc[w][j];
            float e01 = wp ? st.z : st.x;
            float e23 = wp ? st.w : st.y;
            float e = hsel ? e23 : e01;
            float4 hv = hs4[(long)s * 64 + colIdx];
            acc.x += e * hv.x;
            acc.y += e * hv.y;
            acc.z += e * hv.z;
            acc.w += e * hv.w;
        }
        __syncwarp();
    }
#pragma unroll
    for (int off = 16; off > 0; off >>= 1) {
        exsA += __shfl_xor_sync(0xffffffffu, exsA, off);
        exsB += __shfl_xor_sync(0xffffffffu, exsB, off);
    }
    const float den = (hsel ? exsB : exsA) + 1e-16f;

    float v0 = acc.x / den, v1 = acc.y / den, v2 = acc.z / den, v3 = acc.w / den;
    if (mode == 0) {
        float4 b4 = ((const float4*)bias)[colIdx];
        v0 += b4.x; v1 += b4.y; v2 += b4.z; v3 += b4.w;
        v0 = v0 > 0.f ? v0 : expm1f(v0);
        v1 = v1 > 0.f ? v1 : expm1f(v1);
        v2 = v2 > 0.f ? v2 : expm1f(v2);
        v3 = v3 > 0.f ? v3 : expm1f(v3);
        uint2 hi, lo;
        split_pair(v0, v1, hi.x, lo.x);
        split_pair(v2, v3, hi.y, lo.y);
        ((uint2*)g_Ahi)[(long)n * 64 + colIdx] = hi;
        ((uint2*)g_Alo)[(long)n * 64 + colIdx] = lo;
        // a_d for next layer
        const float* p = &vdn[colIdx * 16];
        float q0 = v0 * p[0] + v1 * p[4] + v2 * p[8]  + v3 * p[12];
        float q1 = v0 * p[1] + v1 * p[5] + v2 * p[9]  + v3 * p[13];
        float q2 = v0 * p[2] + v1 * p[6] + v2 * p[10] + v3 * p[14];
        float q3 = v0 * p[3] + v1 * p[7] + v2 * p[11] + v3 * p[15];
#pragma unroll
        for (int off = 16; off > 0; off >>= 1) {
            q0 += __shfl_xor_sync(0xffffffffu, q0, off);
            q1 += __shfl_xor_sync(0xffffffffu, q1, off);
            q2 += __shfl_xor_sync(0xffffffffu, q2, off);
            q3 += __shfl_xor_sync(0xffffffffu, q3, off);
        }
        if (lane < 4) {
            float q = lane == 0 ? q0 : lane == 1 ? q1 : lane == 2 ? q2 : q3;
            s_adp[ni][wp][lane] = q;
        }
        __syncthreads();
        if (tid < 8) {
            int nn = tid >> 2, h = tid & 3;
            g_ad[(blockIdx.x * 2 + nn) * 4 + h] = s_adp[nn][0][h] + s_adp[nn][1][h];
        }
    } else {
        // head-mean accumulate: thread's 4 cols map to out cols 4*(colIdx&15)..+3
        int oc = 4 * (colIdx & 15);
        atomicAdd(&sh[ni][oc],     v0);
        atomicAdd(&sh[ni][oc + 1], v1);
        atomicAdd(&sh[ni][oc + 2], v2);
        atomicAdd(&sh[ni][oc + 3], v3);
        __syncthreads();
        {
            int nn = tid >> 6, cc = tid & 63;
            sh[nn][cc] = 0.25f * sh[nn][cc] + bias[cc];
        }
        __syncthreads();
        if (wp == 0) {   // warps 0 and 2: one warp per node does log_softmax
            float x0 = sh[ni][lane], x1 = sh[ni][lane + 32];
            float a = fmaxf(x0, x1);
#pragma unroll
            for (int off = 16; off > 0; off >>= 1)
                a = fmaxf(a, __shfl_xor_sync(0xffffffffu, a, off));
            float ssum = expf(x0 - a) + expf(x1 - a);
#pragma unroll
            for (int off = 16; off > 0; off >>= 1)
                ssum += __shfl_xor_sync(0xffffffffu, ssum, off);
            float lse = a + logf(ssum);
            out[(long)n * 64 + lane]      = x0 - lse;
            out[(long)n * 64 + lane + 32] = x1 - lse;
        }
    }
}

// ---------------- launch -----------------------------------------------------
extern "C" void kernel_launch(void* const* d_in, const int* in_sizes, int n_in,
                              void* d_out, int out_size) {
    const float* x = (const float*)d_in[0];
    const int* ei = (const int*)d_in[1];
    int e2 = in_sizes[1] / 2;
    const int* src = ei;
    const int* dstp = ei + e2;
    const float* Ws[3] = {(const float*)d_in[2], (const float*)d_in[7],  (const float*)d_in[12]};
    const float* Wd[3] = {(const float*)d_in[3], (const float*)d_in[8],  (const float*)d_in[13]};
    const float* As[3] = {(const float*)d_in[4], (const float*)d_in[9],  (const float*)d_in[14]};
    const float* Ad[3] = {(const float*)d_in[5], (const float*)d_in[10], (const float*)d_in[15]};
    const float* Bb[3] = {(const float*)d_in[6], (const float*)d_in[11], (const float*)d_in[16]};
    float* out = (float*)d_out;

    float* vdPtr = 0;              cudaGetSymbolAddress((void**)&vdPtr, g_vd);
    __nv_bfloat16* bthiPtr = 0;    cudaGetSymbolAddress((void**)&bthiPtr, g_Bthi);
    __nv_bfloat16* btloPtr = 0;    cudaGetSymbolAddress((void**)&btloPtr, g_Btlo);

    const int GEMM_SMEM = 2 * STAGE_W * 4;
    cudaFuncSetAttribute(gemm_mma_kernel, cudaFuncAttributeMaxDynamicSharedMemorySize,
                         GEMM_SMEM);

    int gE = (e2 + 255) / 256;

    clear_deg_kernel<<<(NNODES + 255) / 256, 256>>>();
    count_deg_kernel<<<gE, 256>>>(dstp, e2);
    scan_kernel<<<1, 1024>>>();
    scatter_kernel<<<gE, 256>>>(src, dstp, e2);

    split_x_kernel<<<(NNODES * KD / 4 + 255) / 256, 256>>>(x, NNODES * KD / 4);
    btsplit_all_kernel<<<dim3(KD * KD / 256, 3), 256>>>(Ws[0], Ws[1], Ws[2]);
    for (int l = 0; l < 3; l++)
        compute_vd_kernel<<<1, 1024>>>(Wd[l], Ad[l], l * KD * HEADS);
    ad0_kernel<<<(NNODES + 7) / 8, 256>>>(x);

    for (int l = 0; l < 3; l++) {
        gemm_mma_kernel<<<dim3(MPAD / 128, 2), 256, GEMM_SMEM>>>(
            As[l], bthiPtr + (size_t)l * KD * KD, btloPtr + (size_t)l * KD * KD);
        if (l < 2)
            aggregate_kernel<<<NNODES / 2, 128>>>(Bb[l], vdPtr + (l + 1) * KD * HEADS,
                                                  (float*)0, 0);
        else
            aggregate_kernel<<<NNODES / 2, 128>>>(Bb[l], vdPtr, out, 1);
    }
}

// round 7
// speedup vs baseline: 1.1411x; 1.1411x over previous
#include <cuda_runtime.h>
#include <cuda_bf16.h>
#include <cuda_fp16.h>
#include <math.h>
#include <stdint.h>

#define NNODES 50000
#define MPAD   50048      // 391 * 128
#define KD     256
#define HEADS  4
#define EMAX   1700000

// ---------------- device scratch --------------------------------------------
__device__ __half2         g_hsH[MPAD * KD / 2]; // source transform (fp16!)
__device__ __nv_bfloat16   g_Ahi[MPAD * KD];     // activation split hi
__device__ __nv_bfloat16   g_Alo[MPAD * KD];     // activation split lo
__device__ __nv_bfloat16   g_Bthi[3 * KD * KD];  // W^T split hi, all layers
__device__ __nv_bfloat16   g_Btlo[3 * KD * KD];  // W^T split lo, all layers
__device__ float           g_as[MPAD * HEADS];
__device__ float           g_ad[NNODES * HEADS];
__device__ float           g_vd[3 * KD * HEADS]; // Wd_l @ att_d_l, [l][k][h]
__device__ int             g_deg[NNODES];
__device__ int             g_rowptr[NNODES + 1];
__device__ int             g_cursor[NNODES];
__device__ int             g_srcs[EMAX];         // CSR-ordered SOURCE ids

// ---------------- helpers ----------------------------------------------------
__device__ __forceinline__ void split_pair(float a, float b, unsigned& hi, unsigned& lo) {
    __nv_bfloat16 ha = __float2bfloat16(a), hb = __float2bfloat16(b);
    float ra = a - __bfloat162float(ha);
    float rb = b - __bfloat162float(hb);
    __nv_bfloat162 h2 = __halves2bfloat162(ha, hb);
    __nv_bfloat162 l2 = __floats2bfloat162_rn(ra, rb);
    hi = *reinterpret_cast<unsigned*>(&h2);
    lo = *reinterpret_cast<unsigned*>(&l2);
}

__device__ __forceinline__ void mma_bf16(float* c, const uint32_t* a, const uint32_t* b) {
    asm volatile(
        "mma.sync.aligned.m16n8k16.row.col.f32.bf16.bf16.f32 "
        "{%0,%1,%2,%3},{%4,%5,%6,%7},{%8,%9},{%0,%1,%2,%3};"
        : "+f"(c[0]), "+f"(c[1]), "+f"(c[2]), "+f"(c[3])
        : "r"(a[0]), "r"(a[1]), "r"(a[2]), "r"(a[3]), "r"(b[0]), "r"(b[1]));
}

#define CP_ASYNC16(dst_u32, src_ptr) \
    asm volatile("cp.async.cg.shared.global [%0], [%1], 16;" \
                 :: "r"(dst_u32), "l"(src_ptr))
#define CP_COMMIT() asm volatile("cp.async.commit_group;" ::: "memory")
#define CP_WAIT0()  asm volatile("cp.async.wait_group 0;" ::: "memory")

// ---------------- CSR build --------------------------------------------------
__global__ void clear_deg_kernel() {
    int i = blockIdx.x * blockDim.x + threadIdx.x;
    if (i < NNODES) g_deg[i] = 0;
}
__global__ void count_deg_kernel(const int* __restrict__ dst, int e2) {
    int e = blockIdx.x * blockDim.x + threadIdx.x;
    if (e < e2) atomicAdd(&g_deg[dst[e]], 1);
}
__global__ void scan_kernel() {
    __shared__ int s[1024];
    int t = threadIdx.x;
    const int per = (NNODES + 1023) / 1024;
    int start = t * per;
    int end = start + per; if (end > NNODES) end = NNODES;
    int sum = 0;
    for (int i = start; i < end; i++) sum += g_deg[i];
    s[t] = sum;
    __syncthreads();
    for (int off = 1; off < 1024; off <<= 1) {
        int v = (t >= off) ? s[t - off] : 0;
        __syncthreads();
        s[t] += v;
        __syncthreads();
    }
    int run = (t > 0) ? s[t - 1] : 0;
    for (int i = start; i < end; i++) {
        int d = g_deg[i];
        g_rowptr[i] = run;
        g_cursor[i] = run;
        run += d;
    }
    if (t == 0) g_rowptr[NNODES] = s[1023];
}
__global__ void scatter_kernel(const int* __restrict__ src,
                               const int* __restrict__ dst, int e2) {
    int e = blockIdx.x * blockDim.x + threadIdx.x;
    if (e < e2) {
        int pos = atomicAdd(&g_cursor[dst[e]], 1);
        g_srcs[pos] = src[e];
    }
}

// ---------------- layer-0 pre-split: x -> bf16 hi/lo -------------------------
__global__ void split_x_kernel(const float* __restrict__ A, int nf4) {
    int i = blockIdx.x * blockDim.x + threadIdx.x;
    if (i >= nf4) return;
    float4 v = ((const float4*)A)[i];
    uint2 h, l;
    split_pair(v.x, v.y, h.x, l.x);
    split_pair(v.z, v.w, h.y, l.y);
    ((uint2*)g_Ahi)[i] = h;
    ((uint2*)g_Alo)[i] = l;
}

// ---------------- B transpose+split, all 3 layers ----------------------------
__global__ void btsplit_all_kernel(const float* __restrict__ W0,
                                   const float* __restrict__ W1,
                                   const float* __restrict__ W2) {
    int l = blockIdx.y;
    const float* W = (l == 0) ? W0 : (l == 1) ? W1 : W2;
    int i = blockIdx.x * blockDim.x + threadIdx.x;
    int n = i >> 8, k = i & 255;
    float v = W[k * KD + n];
    __nv_bfloat16 h = __float2bfloat16(v);
    g_Bthi[l * KD * KD + i] = h;
    g_Btlo[l * KD * KD + i] = __float2bfloat16(v - __bfloat162float(h));
}

// ---------------- vd[l][k][h] = sum_c Wd_l[k, h*64+c] * ad_l[h*64+c] ---------
__global__ void compute_vd_kernel(const float* __restrict__ Wd,
                                  const float* __restrict__ ad, int loff) {
    int idx = threadIdx.x;
    int k = idx >> 2;
    int h = idx & 3;
    float s = 0.f;
#pragma unroll 8
    for (int c = 0; c < 64; c++) s += Wd[k * KD + h * 64 + c] * ad[h * 64 + c];
    g_vd[loff + k * 4 + h] = s;
}

// ---------------- layer-0 a_d = x . vd0  (warp per node) ---------------------
__global__ void __launch_bounds__(256) ad0_kernel(const float* __restrict__ X) {
    __shared__ float svd[KD * 4];
    int tid = threadIdx.x;
    for (int i = tid; i < KD * 4; i += 256) svd[i] = g_vd[i];
    __syncthreads();
    int warp = tid >> 5, lane = tid & 31;
    int n = blockIdx.x * 8 + warp;
    if (n >= NNODES) return;
    const float4* x4 = (const float4*)X + (long)n * 64;
    float a0 = 0.f, a1 = 0.f, a2 = 0.f, a3 = 0.f;
#pragma unroll
    for (int g4 = 0; g4 < 2; g4++) {
        float4 xv = x4[lane * 2 + g4];
        const float* p = &svd[(lane * 8 + g4 * 4) * 4];
        a0 += xv.x * p[0] + xv.y * p[4] + xv.z * p[8]  + xv.w * p[12];
        a1 += xv.x * p[1] + xv.y * p[5] + xv.z * p[9]  + xv.w * p[13];
        a2 += xv.x * p[2] + xv.y * p[6] + xv.z * p[10] + xv.w * p[14];
        a3 += xv.x * p[3] + xv.y * p[7] + xv.z * p[11] + xv.w * p[15];
    }
#pragma unroll
    for (int off = 16; off > 0; off >>= 1) {
        a0 += __shfl_xor_sync(0xffffffffu, a0, off);
        a1 += __shfl_xor_sync(0xffffffffu, a1, off);
        a2 += __shfl_xor_sync(0xffffffffu, a2, off);
        a3 += __shfl_xor_sync(0xffffffffu, a3, off);
    }
    if (lane == 0) ((float4*)g_ad)[n] = make_float4(a0, a1, a2, a3);
}

// ---------------- GEMM: hs(fp16) = A @ W_l, cp.async 2-stage, fused a_s ------
#define S32 20
#define STAGE_W 10240
__global__ void __launch_bounds__(256) gemm_mma_kernel(const float* __restrict__ attS,
                                                       const __nv_bfloat16* __restrict__ Bh,
                                                       const __nv_bfloat16* __restrict__ Bl) {
    extern __shared__ uint32_t smem_u[];
    __shared__ float s_as[128][2];
    const int tid = threadIdx.x;
    const int wid = tid >> 5, lane = tid & 31;
    const int wm = wid >> 2, wn = wid & 3;
    const int row0 = blockIdx.x * 128;
    const int n0 = blockIdx.y * 128;
    const int g8 = lane >> 2, tq = lane & 3;
    const uint32_t smem_b = (uint32_t)__cvta_generic_to_shared(smem_u);

    ((float*)s_as)[tid] = 0.f;

    const int lr0 = tid >> 2;
    const int lc4 = tid & 3;
    float c[4][4][4];
#pragma unroll
    for (int mt = 0; mt < 4; mt++)
#pragma unroll
        for (int nt = 0; nt < 4; nt++)
#pragma unroll
            for (int j = 0; j < 4; j++) c[mt][nt][j] = 0.f;

#define LOAD_CHUNK(stg, cc) do {                                               \
    int k0 = (cc) * 32;                                                        \
    _Pragma("unroll")                                                          \
    for (int i = 0; i < 2; i++) {                                              \
        int r = lr0 + i * 64;                                                  \
        long ga = (long)(row0 + r) * KD + k0 + lc4 * 8;                        \
        long gb = (long)(n0 + r) * KD + k0 + lc4 * 8;                          \
        uint32_t so = smem_b + ((stg) * STAGE_W + r * S32 + lc4 * 4) * 4;      \
        CP_ASYNC16(so,            g_Ahi + ga);                                 \
        CP_ASYNC16(so + 2560 * 4, g_Alo + ga);                                 \
        CP_ASYNC16(so + 5120 * 4, Bh + gb);                                    \
        CP_ASYNC16(so + 7680 * 4, Bl + gb);                                    \
    }                                                                          \
} while (0)

    LOAD_CHUNK(0, 0);
    CP_COMMIT();

    for (int cch = 0; cch < 8; cch++) {
        const int stg = cch & 1;
        CP_WAIT0();
        __syncthreads();
        if (cch < 7) { LOAD_CHUNK(stg ^ 1, cch + 1); CP_COMMIT(); }
        const uint32_t* sAh = smem_u + stg * STAGE_W;
        const uint32_t* sAl = sAh + 2560;
        const uint32_t* sBh = sAh + 5120;
        const uint32_t* sBl = sAh + 7680;
#pragma unroll
        for (int kk = 0; kk < 2; kk++) {
            const int kb = kk * 8;
            uint32_t ah[4][4], al[4][4], bh[4][2], bl[4][2];
#pragma unroll
            for (int mt = 0; mt < 4; mt++) {
                int r = (wm * 64 + mt * 16 + g8) * S32 + kb + tq;
                int r8 = r + 8 * S32;
                ah[mt][0] = sAh[r];     ah[mt][1] = sAh[r8];
                ah[mt][2] = sAh[r + 4]; ah[mt][3] = sAh[r8 + 4];
                al[mt][0] = sAl[r];     al[mt][1] = sAl[r8];
                al[mt][2] = sAl[r + 4]; al[mt][3] = sAl[r8 + 4];
            }
#pragma unroll
            for (int nt = 0; nt < 4; nt++) {
                int r = (wn * 32 + nt * 8 + g8) * S32 + kb + tq;
                bh[nt][0] = sBh[r]; bh[nt][1] = sBh[r + 4];
                bl[nt][0] = sBl[r]; bl[nt][1] = sBl[r + 4];
            }
#pragma unroll
            for (int mt = 0; mt < 4; mt++)
#pragma unroll
                for (int nt = 0; nt < 4; nt++) {
                    mma_bf16(c[mt][nt], ah[mt], bh[nt]);
                    mma_bf16(c[mt][nt], ah[mt], bl[nt]);
                    mma_bf16(c[mt][nt], al[mt], bh[nt]);
                }
        }
        __syncthreads();
    }

    // epilogue 1: fragments -> g_hsH (fp16)
#pragma unroll
    for (int mt = 0; mt < 4; mt++) {
        int r = row0 + wm * 64 + mt * 16 + g8;
#pragma unroll
        for (int nt = 0; nt < 4; nt++) {
            int h2i = 64 * blockIdx.y + wn * 16 + nt * 4 + tq;  // half2 index in row
            g_hsH[(long)r * 128 + h2i]       = __floats2half2_rn(c[mt][nt][0], c[mt][nt][1]);
            g_hsH[(long)(r + 8) * 128 + h2i] = __floats2half2_rn(c[mt][nt][2], c[mt][nt][3]);
        }
    }
    // epilogue 2: fused a_s via block-shared reduction
    {
        float p0[4] = {0.f, 0.f, 0.f, 0.f};
        float p1[4] = {0.f, 0.f, 0.f, 0.f};
#pragma unroll
        for (int nt = 0; nt < 4; nt++) {
            int col = n0 + wn * 32 + nt * 8 + tq * 2;
            float a0 = attS[col], a1 = attS[col + 1];
#pragma unroll
            for (int mt = 0; mt < 4; mt++) {
                p0[mt] += c[mt][nt][0] * a0 + c[mt][nt][1] * a1;
                p1[mt] += c[mt][nt][2] * a0 + c[mt][nt][3] * a1;
            }
        }
        int hl = wn >> 1;
#pragma unroll
        for (int mt = 0; mt < 4; mt++) {
            p0[mt] += __shfl_xor_sync(0xffffffffu, p0[mt], 1);
            p0[mt] += __shfl_xor_sync(0xffffffffu, p0[mt], 2);
            p1[mt] += __shfl_xor_sync(0xffffffffu, p1[mt], 1);
            p1[mt] += __shfl_xor_sync(0xffffffffu, p1[mt], 2);
            if (tq == 0) {
                int rl = wm * 64 + mt * 16 + g8;
                atomicAdd(&s_as[rl][hl], p0[mt]);
                atomicAdd(&s_as[rl + 8][hl], p1[mt]);
            }
        }
        __syncthreads();
        int rl = tid >> 1, h2 = tid & 1;
        g_as[(row0 + rl) * 4 + blockIdx.y * 2 + h2] = s_as[rl][h2];
    }
}

// ---------------- aggregation: R5 structure, fp16 gather ---------------------
// 128 thr/node, warp-per-head, per-warp staging, fused denominator.
// mode 0: elu(acc/den + bias) -> Ahi/Alo split; a_d(next) via vdn
// mode 1: head-mean + b2 + log_softmax -> out[n,64]
__global__ void __launch_bounds__(128) aggregate_kernel(const float* __restrict__ bias,
                                                        const float* __restrict__ vdn,
                                                        float* __restrict__ out,
                                                        int mode) {
    __shared__ float2 stage[4][32];
    __shared__ float  s_adp[4][4];
    __shared__ float  sh[256];
    __shared__ float  s_red[2];

    const int n = blockIdx.x;
    const int tid = threadIdx.x;
    const int w = tid >> 5, lane = tid & 31;
    const int base = g_rowptr[n];
    const int deg = g_rowptr[n + 1] - base;

    const float adw = g_ad[n * 4 + w];
    const __half2* __restrict__ hs2 = g_hsH;
    const int colIdx = w * 32 + lane;       // half2 index within row (0..127)

    float2 acc = make_float2(0.f, 0.f);
    float exsum = 0.f;
    for (int cs = 0; cs < deg; cs += 32) {
        int m = deg - cs; if (m > 32) m = 32;
        float ex = 0.f; int sI = 0;
        if (lane < m) {
            sI = g_srcs[base + cs + lane];
            float al = g_as[sI * 4 + w] + adw;
            al = al > 0.f ? al : 0.2f * al;
            ex = __expf(al);
            exsum += ex;
        }
        stage[w][lane] = make_float2(ex, __int_as_float(sI));
        __syncwarp();
#pragma unroll 4
        for (int j = 0; j < m; j++) {
            float2 st = stage[w][j];
            int s = __float_as_int(st.y);
            float2 hv = __half22float2(hs2[(long)s * 128 + colIdx]);
            acc.x += st.x * hv.x;
            acc.y += st.x * hv.y;
        }
        __syncwarp();
    }
#pragma unroll
    for (int off = 16; off > 0; off >>= 1)
        exsum += __shfl_xor_sync(0xffffffffu, exsum, off);
    const float den = exsum + 1e-16f;

    const int col0 = w * 64 + lane * 2;
    float v0 = acc.x / den;
    float v1 = acc.y / den;
    if (mode == 0) {
        v0 += bias[col0];
        v1 += bias[col0 + 1];
        v0 = v0 > 0.f ? v0 : expm1f(v0);
        v1 = v1 > 0.f ? v1 : expm1f(v1);
        unsigned hi, lo;
        split_pair(v0, v1, hi, lo);
        ((uint32_t*)g_Ahi)[n * 128 + colIdx] = hi;
        ((uint32_t*)g_Alo)[n * 128 + colIdx] = lo;
        // a_d for next layer
        const float* p0 = &vdn[col0 * 4];
        float q0 = v0 * p0[0] + v1 * p0[4];
        float q1 = v0 * p0[1] + v1 * p0[5];
        float q2 = v0 * p0[2] + v1 * p0[6];
        float q3 = v0 * p0[3] + v1 * p0[7];
#pragma unroll
        for (int off = 16; off > 0; off >>= 1) {
            q0 += __shfl_xor_sync(0xffffffffu, q0, off);
            q1 += __shfl_xor_sync(0xffffffffu, q1, off);
            q2 += __shfl_xor_sync(0xffffffffu, q2, off);
            q3 += __shfl_xor_sync(0xffffffffu, q3, off);
        }
        if (lane < 4) {
            float q = lane == 0 ? q0 : lane == 1 ? q1 : lane == 2 ? q2 : q3;
            s_adp[w][lane] = q;
        }
        __syncthreads();
        if (tid < 4)
            g_ad[n * 4 + tid] = s_adp[0][tid] + s_adp[1][tid] + s_adp[2][tid] + s_adp[3][tid];
    } else {
        sh[col0] = v0;
        sh[col0 + 1] = v1;
        __syncthreads();
        if (tid < 64)
            sh[tid] = 0.25f * (sh[tid] + sh[tid + 64] + sh[tid + 128] + sh[tid + 192]) + bias[tid];
        __syncthreads();
        if (tid < 32) {
            float a = fmaxf(sh[tid], sh[tid + 32]);
#pragma unroll
            for (int off = 16; off > 0; off >>= 1)
                a = fmaxf(a, __shfl_xor_sync(0xffffffffu, a, off));
            if (tid == 0) s_red[0] = a;
        }
        __syncthreads();
        if (tid < 32) {
            float mx = s_red[0];
            float a = expf(sh[tid] - mx) + expf(sh[tid + 32] - mx);
#pragma unroll
            for (int off = 16; off > 0; off >>= 1)
                a += __shfl_xor_sync(0xffffffffu, a, off);
            if (tid == 0) s_red[1] = a;
        }
        __syncthreads();
        if (tid < 64) out[(long)n * 64 + tid] = sh[tid] - s_red[0] - logf(s_red[1]);
    }
}

// ---------------- launch -----------------------------------------------------
extern "C" void kernel_launch(void* const* d_in, const int* in_sizes, int n_in,
                              void* d_out, int out_size) {
    const float* x = (const float*)d_in[0];
    const int* ei = (const int*)d_in[1];
    int e2 = in_sizes[1] / 2;
    const int* src = ei;
    const int* dstp = ei + e2;
    const float* Ws[3] = {(const float*)d_in[2], (const float*)d_in[7],  (const float*)d_in[12]};
    const float* Wd[3] = {(const float*)d_in[3], (const float*)d_in[8],  (const float*)d_in[13]};
    const float* As[3] = {(const float*)d_in[4], (const float*)d_in[9],  (const float*)d_in[14]};
    const float* Ad[3] = {(const float*)d_in[5], (const float*)d_in[10], (const float*)d_in[15]};
    const float* Bb[3] = {(const float*)d_in[6], (const float*)d_in[11], (const float*)d_in[16]};
    float* out = (float*)d_out;

    float* vdPtr = 0;              cudaGetSymbolAddress((void**)&vdPtr, g_vd);
    __nv_bfloat16* bthiPtr = 0;    cudaGetSymbolAddress((void**)&bthiPtr, g_Bthi);
    __nv_bfloat16* btloPtr = 0;    cudaGetSymbolAddress((void**)&btloPtr, g_Btlo);

    const int GEMM_SMEM = 2 * STAGE_W * 4;
    cudaFuncSetAttribute(gemm_mma_kernel, cudaFuncAttributeMaxDynamicSharedMemorySize,
                         GEMM_SMEM);

    int gE = (e2 + 255) / 256;

    clear_deg_kernel<<<(NNODES + 255) / 256, 256>>>();
    count_deg_kernel<<<gE, 256>>>(dstp, e2);
    scan_kernel<<<1, 1024>>>();
    scatter_kernel<<<gE, 256>>>(src, dstp, e2);

    split_x_kernel<<<(NNODES * KD / 4 + 255) / 256, 256>>>(x, NNODES * KD / 4);
    btsplit_all_kernel<<<dim3(KD * KD / 256, 3), 256>>>(Ws[0], Ws[1], Ws[2]);
    for (int l = 0; l < 3; l++)
        compute_vd_kernel<<<1, 1024>>>(Wd[l], Ad[l], l * KD * HEADS);
    ad0_kernel<<<(NNODES + 7) / 8, 256>>>(x);

    for (int l = 0; l < 3; l++) {
        gemm_mma_kernel<<<dim3(MPAD / 128, 2), 256, GEMM_SMEM>>>(
            As[l], bthiPtr + (size_t)l * KD * KD, btloPtr + (size_t)l * KD * KD);
        if (l < 2)
            aggregate_kernel<<<NNODES, 128>>>(Bb[l], vdPtr + (l + 1) * KD * HEADS,
                                              (float*)0, 0);
        else
            aggregate_kernel<<<NNODES, 128>>>(Bb[l], vdPtr, out, 1);
    }
}

// round 8
// speedup vs baseline: 1.2744x; 1.1168x over previous
#include <cuda_runtime.h>
#include <cuda_bf16.h>
#include <cuda_fp16.h>
#include <math.h>
#include <stdint.h>

#define NNODES 50000
#define MPAD   50048      // 391 * 128
#define KD     256
#define HEADS  4
#define EMAX   1700000

// ---------------- device scratch --------------------------------------------
__device__ __half2         g_hsH[MPAD * KD / 2]; // source transform (fp16)
__device__ __nv_bfloat16   g_Ahi[MPAD * KD];     // activation split hi
__device__ __nv_bfloat16   g_Alo[MPAD * KD];     // activation split lo
__device__ __nv_bfloat16   g_Bthi[3 * KD * KD];  // W^T split hi, all layers
__device__ __nv_bfloat16   g_Btlo[3 * KD * KD];  // W^T split lo, all layers
__device__ float           g_as[MPAD * HEADS];
__device__ float           g_ad[NNODES * HEADS];
__device__ float           g_vd[3 * KD * HEADS]; // Wd_l @ att_d_l, [l][k][h]
__device__ int             g_deg[NNODES];
__device__ int             g_rowptr[NNODES + 1];
__device__ int             g_cursor[NNODES];
__device__ int             g_srcs[EMAX];         // CSR-ordered SOURCE ids

// ---------------- helpers ----------------------------------------------------
__device__ __forceinline__ void split_pair(float a, float b, unsigned& hi, unsigned& lo) {
    __nv_bfloat16 ha = __float2bfloat16(a), hb = __float2bfloat16(b);
    float ra = a - __bfloat162float(ha);
    float rb = b - __bfloat162float(hb);
    __nv_bfloat162 h2 = __halves2bfloat162(ha, hb);
    __nv_bfloat162 l2 = __floats2bfloat162_rn(ra, rb);
    hi = *reinterpret_cast<unsigned*>(&h2);
    lo = *reinterpret_cast<unsigned*>(&l2);
}

__device__ __forceinline__ void mma_bf16(float* c, const uint32_t* a, const uint32_t* b) {
    asm volatile(
        "mma.sync.aligned.m16n8k16.row.col.f32.bf16.bf16.f32 "
        "{%0,%1,%2,%3},{%4,%5,%6,%7},{%8,%9},{%0,%1,%2,%3};"
        : "+f"(c[0]), "+f"(c[1]), "+f"(c[2]), "+f"(c[3])
        : "r"(a[0]), "r"(a[1]), "r"(a[2]), "r"(a[3]), "r"(b[0]), "r"(b[1]));
}

#define CP_ASYNC16(dst_u32, src_ptr) \
    asm volatile("cp.async.cg.shared.global [%0], [%1], 16;" \
                 :: "r"(dst_u32), "l"(src_ptr))
#define CP_COMMIT() asm volatile("cp.async.commit_group;" ::: "memory")
#define CP_WAIT0()  asm volatile("cp.async.wait_group 0;" ::: "memory")

// ---------------- CSR build --------------------------------------------------
__global__ void clear_deg_kernel() {
    int i = blockIdx.x * blockDim.x + threadIdx.x;
    if (i < NNODES) g_deg[i] = 0;
}
__global__ void count_deg_kernel(const int* __restrict__ dst, int e2) {
    int e = blockIdx.x * blockDim.x + threadIdx.x;
    if (e < e2) atomicAdd(&g_deg[dst[e]], 1);
}
__global__ void scan_kernel() {
    __shared__ int s[1024];
    int t = threadIdx.x;
    const int per = (NNODES + 1023) / 1024;
    int start = t * per;
    int end = start + per; if (end > NNODES) end = NNODES;
    int sum = 0;
    for (int i = start; i < end; i++) sum += g_deg[i];
    s[t] = sum;
    __syncthreads();
    for (int off = 1; off < 1024; off <<= 1) {
        int v = (t >= off) ? s[t - off] : 0;
        __syncthreads();
        s[t] += v;
        __syncthreads();
    }
    int run = (t > 0) ? s[t - 1] : 0;
    for (int i = start; i < end; i++) {
        int d = g_deg[i];
        g_rowptr[i] = run;
        g_cursor[i] = run;
        run += d;
    }
    if (t == 0) g_rowptr[NNODES] = s[1023];
}
__global__ void scatter_kernel(const int* __restrict__ src,
                               const int* __restrict__ dst, int e2) {
    int e = blockIdx.x * blockDim.x + threadIdx.x;
    if (e < e2) {
        int pos = atomicAdd(&g_cursor[dst[e]], 1);
        g_srcs[pos] = src[e];
    }
}

// ---------------- fused: x -> Ahi/Alo split AND layer-0 a_d ------------------
__global__ void __launch_bounds__(256) prep_x_kernel(const float* __restrict__ X) {
    __shared__ float svd[KD * 4];
    int tid = threadIdx.x;
    for (int i = tid; i < KD * 4; i += 256) svd[i] = g_vd[i];
    __syncthreads();
    int warp = tid >> 5, lane = tid & 31;
    int n = blockIdx.x * 8 + warp;
    if (n >= NNODES) return;
    float a0 = 0.f, a1 = 0.f, a2 = 0.f, a3 = 0.f;
#pragma unroll
    for (int g4 = 0; g4 < 2; g4++) {
        int f4i = n * 64 + lane * 2 + g4;
        float4 xv = ((const float4*)X)[f4i];
        uint2 h, l;
        split_pair(xv.x, xv.y, h.x, l.x);
        split_pair(xv.z, xv.w, h.y, l.y);
        ((uint2*)g_Ahi)[f4i] = h;
        ((uint2*)g_Alo)[f4i] = l;
        const float* p = &svd[(lane * 8 + g4 * 4) * 4];
        a0 += xv.x * p[0] + xv.y * p[4] + xv.z * p[8]  + xv.w * p[12];
        a1 += xv.x * p[1] + xv.y * p[5] + xv.z * p[9]  + xv.w * p[13];
        a2 += xv.x * p[2] + xv.y * p[6] + xv.z * p[10] + xv.w * p[14];
        a3 += xv.x * p[3] + xv.y * p[7] + xv.z * p[11] + xv.w * p[15];
    }
#pragma unroll
    for (int off = 16; off > 0; off >>= 1) {
        a0 += __shfl_xor_sync(0xffffffffu, a0, off);
        a1 += __shfl_xor_sync(0xffffffffu, a1, off);
        a2 += __shfl_xor_sync(0xffffffffu, a2, off);
        a3 += __shfl_xor_sync(0xffffffffu, a3, off);
    }
    if (lane == 0) ((float4*)g_ad)[n] = make_float4(a0, a1, a2, a3);
}

// ---------------- B transpose+split, all 3 layers ----------------------------
__global__ void btsplit_all_kernel(const float* __restrict__ W0,
                                   const float* __restrict__ W1,
                                   const float* __restrict__ W2) {
    int l = blockIdx.y;
    const float* W = (l == 0) ? W0 : (l == 1) ? W1 : W2;
    int i = blockIdx.x * blockDim.x + threadIdx.x;
    int n = i >> 8, k = i & 255;
    float v = W[k * KD + n];
    __nv_bfloat16 h = __float2bfloat16(v);
    g_Bthi[l * KD * KD + i] = h;
    g_Btlo[l * KD * KD + i] = __float2bfloat16(v - __bfloat162float(h));
}

// ---------------- vd for all layers in one launch ----------------------------
__global__ void compute_vd_all_kernel(const float* __restrict__ Wd0,
                                      const float* __restrict__ Wd1,
                                      const float* __restrict__ Wd2,
                                      const float* __restrict__ ad0,
                                      const float* __restrict__ ad1,
                                      const float* __restrict__ ad2) {
    int l = blockIdx.x;
    const float* Wd = (l == 0) ? Wd0 : (l == 1) ? Wd1 : Wd2;
    const float* ad = (l == 0) ? ad0 : (l == 1) ? ad1 : ad2;
    int idx = threadIdx.x;
    int k = idx >> 2;
    int h = idx & 3;
    float s = 0.f;
#pragma unroll 8
    for (int c = 0; c < 64; c++) s += Wd[k * KD + h * 64 + c] * ad[h * 64 + c];
    g_vd[l * KD * HEADS + k * 4 + h] = s;
}

// ---------------- GEMM: hs(fp16) = A @ W_l, cp.async 2-stage, fused a_s ------
#define S32 20
#define STAGE_W 10240
__global__ void __launch_bounds__(256) gemm_mma_kernel(const float* __restrict__ attS,
                                                       const __nv_bfloat16* __restrict__ Bh,
                                                       const __nv_bfloat16* __restrict__ Bl) {
    extern __shared__ uint32_t smem_u[];
    __shared__ float s_as[128][2];
    const int tid = threadIdx.x;
    const int wid = tid >> 5, lane = tid & 31;
    const int wm = wid >> 2, wn = wid & 3;
    const int row0 = blockIdx.x * 128;
    const int n0 = blockIdx.y * 128;
    const int g8 = lane >> 2, tq = lane & 3;
    const uint32_t smem_b = (uint32_t)__cvta_generic_to_shared(smem_u);

    ((float*)s_as)[tid] = 0.f;

    const int lr0 = tid >> 2;
    const int lc4 = tid & 3;
    float c[4][4][4];
#pragma unroll
    for (int mt = 0; mt < 4; mt++)
#pragma unroll
        for (int nt = 0; nt < 4; nt++)
#pragma unroll
            for (int j = 0; j < 4; j++) c[mt][nt][j] = 0.f;

#define LOAD_CHUNK(stg, cc) do {                                               \
    int k0 = (cc) * 32;                                                        \
    _Pragma("unroll")                                                          \
    for (int i = 0; i < 2; i++) {                                              \
        int r = lr0 + i * 64;                                                  \
        long ga = (long)(row0 + r) * KD + k0 + lc4 * 8;                        \
        long gb = (long)(n0 + r) * KD + k0 + lc4 * 8;                          \
        uint32_t so = smem_b + ((stg) * STAGE_W + r * S32 + lc4 * 4) * 4;      \
        CP_ASYNC16(so,            g_Ahi + ga);                                 \
        CP_ASYNC16(so + 2560 * 4, g_Alo + ga);                                 \
        CP_ASYNC16(so + 5120 * 4, Bh + gb);                                    \
        CP_ASYNC16(so + 7680 * 4, Bl + gb);                                    \
    }                                                                          \
} while (0)

    LOAD_CHUNK(0, 0);
    CP_COMMIT();

    for (int cch = 0; cch < 8; cch++) {
        const int stg = cch & 1;
        CP_WAIT0();
        __syncthreads();
        if (cch < 7) { LOAD_CHUNK(stg ^ 1, cch + 1); CP_COMMIT(); }
        const uint32_t* sAh = smem_u + stg * STAGE_W;
        const uint32_t* sAl = sAh + 2560;
        const uint32_t* sBh = sAh + 5120;
        const uint32_t* sBl = sAh + 7680;
#pragma unroll
        for (int kk = 0; kk < 2; kk++) {
            const int kb = kk * 8;
            uint32_t ah[4][4], al[4][4], bh[4][2], bl[4][2];
#pragma unroll
            for (int mt = 0; mt < 4; mt++) {
                int r = (wm * 64 + mt * 16 + g8) * S32 + kb + tq;
                int r8 = r + 8 * S32;
                ah[mt][0] = sAh[r];     ah[mt][1] = sAh[r8];
                ah[mt][2] = sAh[r + 4]; ah[mt][3] = sAh[r8 + 4];
                al[mt][0] = sAl[r];     al[mt][1] = sAl[r8];
                al[mt][2] = sAl[r + 4]; al[mt][3] = sAl[r8 + 4];
            }
#pragma unroll
            for (int nt = 0; nt < 4; nt++) {
                int r = (wn * 32 + nt * 8 + g8) * S32 + kb + tq;
                bh[nt][0] = sBh[r]; bh[nt][1] = sBh[r + 4];
                bl[nt][0] = sBl[r]; bl[nt][1] = sBl[r + 4];
            }
#pragma unroll
            for (int mt = 0; mt < 4; mt++)
#pragma unroll
                for (int nt = 0; nt < 4; nt++) {
                    mma_bf16(c[mt][nt], ah[mt], bh[nt]);
                    mma_bf16(c[mt][nt], ah[mt], bl[nt]);
                    mma_bf16(c[mt][nt], al[mt], bh[nt]);
                }
        }
        __syncthreads();
    }

    // epilogue 1: fragments -> g_hsH (fp16)
#pragma unroll
    for (int mt = 0; mt < 4; mt++) {
        int r = row0 + wm * 64 + mt * 16 + g8;
#pragma unroll
        for (int nt = 0; nt < 4; nt++) {
            int h2i = 64 * blockIdx.y + wn * 16 + nt * 4 + tq;
            g_hsH[(long)r * 128 + h2i]       = __floats2half2_rn(c[mt][nt][0], c[mt][nt][1]);
            g_hsH[(long)(r + 8) * 128 + h2i] = __floats2half2_rn(c[mt][nt][2], c[mt][nt][3]);
        }
    }
    // epilogue 2: fused a_s via block-shared reduction
    {
        float p0[4] = {0.f, 0.f, 0.f, 0.f};
        float p1[4] = {0.f, 0.f, 0.f, 0.f};
#pragma unroll
        for (int nt = 0; nt < 4; nt++) {
            int col = n0 + wn * 32 + nt * 8 + tq * 2;
            float a0 = attS[col], a1 = attS[col + 1];
#pragma unroll
            for (int mt = 0; mt < 4; mt++) {
                p0[mt] += c[mt][nt][0] * a0 + c[mt][nt][1] * a1;
                p1[mt] += c[mt][nt][2] * a0 + c[mt][nt][3] * a1;
            }
        }
        int hl = wn >> 1;
#pragma unroll
        for (int mt = 0; mt < 4; mt++) {
            p0[mt] += __shfl_xor_sync(0xffffffffu, p0[mt], 1);
            p0[mt] += __shfl_xor_sync(0xffffffffu, p0[mt], 2);
            p1[mt] += __shfl_xor_sync(0xffffffffu, p1[mt], 1);
            p1[mt] += __shfl_xor_sync(0xffffffffu, p1[mt], 2);
            if (tq == 0) {
                int rl = wm * 64 + mt * 16 + g8;
                atomicAdd(&s_as[rl][hl], p0[mt]);
                atomicAdd(&s_as[rl + 8][hl], p1[mt]);
            }
        }
        __syncthreads();
        int rl = tid >> 1, h2 = tid & 1;
        g_as[(row0 + rl) * 4 + blockIdx.y * 2 + h2] = s_as[rl][h2];
    }
}

// ---------------- aggregation: 64-edge staging, unroll-8 gather --------------
// 128 thr/node, warp-per-head, per-warp staging (2 edges/lane), fused denom.
__global__ void __launch_bounds__(128) aggregate_kernel(const float* __restrict__ bias,
                                                        const float* __restrict__ vdn,
                                                        float* __restrict__ out,
                                                        int mode) {
    __shared__ float s_ex[4][64];
    __shared__ int   s_si[4][64];
    __shared__ float s_adp[4][4];
    __shared__ float sh[256];
    __shared__ float s_red[2];

    const int n = blockIdx.x;
    const int tid = threadIdx.x;
    const int w = tid >> 5, lane = tid & 31;
    const int base = g_rowptr[n];
    const int deg = g_rowptr[n + 1] - base;

    const float adw = g_ad[n * 4 + w];
    const __half2* __restrict__ hs2 = g_hsH;
    const int colIdx = w * 32 + lane;

    float a0x = 0.f, a0y = 0.f, a1x = 0.f, a1y = 0.f;
    float exsum = 0.f;
    for (int cs = 0; cs < deg; cs += 64) {
        int m = deg - cs; if (m > 64) m = 64;
        if (lane < m) {
            int sI = g_srcs[base + cs + lane];
            float al = g_as[sI * 4 + w] + adw;
            al = al > 0.f ? al : 0.2f * al;
            float ex = __expf(al);
            exsum += ex;
            s_ex[w][lane] = ex;
            s_si[w][lane] = sI;
        }
        if (lane + 32 < m) {
            int sI = g_srcs[base + cs + lane + 32];
            float al = g_as[sI * 4 + w] + adw;
            al = al > 0.f ? al : 0.2f * al;
            float ex = __expf(al);
            exsum += ex;
            s_ex[w][lane + 32] = ex;
            s_si[w][lane + 32] = sI;
        }
        __syncwarp();
        int j = 0;
        for (; j + 8 <= m; j += 8) {
#pragma unroll
            for (int u = 0; u < 8; u += 2) {
                float e0 = s_ex[w][j + u];     int s0 = s_si[w][j + u];
                float e1 = s_ex[w][j + u + 1]; int s1 = s_si[w][j + u + 1];
                float2 h0 = __half22float2(hs2[(long)s0 * 128 + colIdx]);
                float2 h1 = __half22float2(hs2[(long)s1 * 128 + colIdx]);
                a0x += e0 * h0.x; a0y += e0 * h0.y;
                a1x += e1 * h1.x; a1y += e1 * h1.y;
            }
        }
        for (; j < m; j++) {
            float e0 = s_ex[w][j]; int s0 = s_si[w][j];
            float2 h0 = __half22float2(hs2[(long)s0 * 128 + colIdx]);
            a0x += e0 * h0.x; a0y += e0 * h0.y;
        }
        __syncwarp();
    }
#pragma unroll
    for (int off = 16; off > 0; off >>= 1)
        exsum += __shfl_xor_sync(0xffffffffu, exsum, off);
    const float den = exsum + 1e-16f;

    const int col0 = w * 64 + lane * 2;
    float v0 = (a0x + a1x) / den;
    float v1 = (a0y + a1y) / den;
    if (mode == 0) {
        v0 += bias[col0];
        v1 += bias[col0 + 1];
        v0 = v0 > 0.f ? v0 : expm1f(v0);
        v1 = v1 > 0.f ? v1 : expm1f(v1);
        unsigned hi, lo;
        split_pair(v0, v1, hi, lo);
        ((uint32_t*)g_Ahi)[n * 128 + colIdx] = hi;
        ((uint32_t*)g_Alo)[n * 128 + colIdx] = lo;
        const float* p0 = &vdn[col0 * 4];
        float q0 = v0 * p0[0] + v1 * p0[4];
        float q1 = v0 * p0[1] + v1 * p0[5];
        float q2 = v0 * p0[2] + v1 * p0[6];
        float q3 = v0 * p0[3] + v1 * p0[7];
#pragma unroll
        for (int off = 16; off > 0; off >>= 1) {
            q0 += __shfl_xor_sync(0xffffffffu, q0, off);
            q1 += __shfl_xor_sync(0xffffffffu, q1, off);
            q2 += __shfl_xor_sync(0xffffffffu, q2, off);
            q3 += __shfl_xor_sync(0xffffffffu, q3, off);
        }
        if (lane < 4) {
            float q = lane == 0 ? q0 : lane == 1 ? q1 : lane == 2 ? q2 : q3;
            s_adp[w][lane] = q;
        }
        __syncthreads();
        if (tid < 4)
            g_ad[n * 4 + tid] = s_adp[0][tid] + s_adp[1][tid] + s_adp[2][tid] + s_adp[3][tid];
    } else {
        sh[col0] = v0;
        sh[col0 + 1] = v1;
        __syncthreads();
        if (tid < 64)
            sh[tid] = 0.25f * (sh[tid] + sh[tid + 64] + sh[tid + 128] + sh[tid + 192]) + bias[tid];
        __syncthreads();
        if (tid < 32) {
            float a = fmaxf(sh[tid], sh[tid + 32]);
#pragma unroll
            for (int off = 16; off > 0; off >>= 1)
                a = fmaxf(a, __shfl_xor_sync(0xffffffffu, a, off));
            if (tid == 0) s_red[0] = a;
        }
        __syncthreads();
        if (tid < 32) {
            float mx = s_red[0];
            float a = expf(sh[tid] - mx) + expf(sh[tid + 32] - mx);
#pragma unroll
            for (int off = 16; off > 0; off >>= 1)
                a += __shfl_xor_sync(0xffffffffu, a, off);
            if (tid == 0) s_red[1] = a;
        }
        __syncthreads();
        if (tid < 64) out[(long)n * 64 + tid] = sh[tid] - s_red[0] - logf(s_red[1]);
    }
}

// ---------------- launch -----------------------------------------------------
extern "C" void kernel_launch(void* const* d_in, const int* in_sizes, int n_in,
                              void* d_out, int out_size) {
    const float* x = (const float*)d_in[0];
    const int* ei = (const int*)d_in[1];
    int e2 = in_sizes[1] / 2;
    const int* src = ei;
    const int* dstp = ei + e2;
    const float* Ws[3] = {(const float*)d_in[2], (const float*)d_in[7],  (const float*)d_in[12]};
    const float* Wd[3] = {(const float*)d_in[3], (const float*)d_in[8],  (const float*)d_in[13]};
    const float* As[3] = {(const float*)d_in[4], (const float*)d_in[9],  (const float*)d_in[14]};
    const float* Ad[3] = {(const float*)d_in[5], (const float*)d_in[10], (const float*)d_in[15]};
    const float* Bb[3] = {(const float*)d_in[6], (const float*)d_in[11], (const float*)d_in[16]};
    float* out = (float*)d_out;

    float* vdPtr = 0;              cudaGetSymbolAddress((void**)&vdPtr, g_vd);
    __nv_bfloat16* bthiPtr = 0;    cudaGetSymbolAddress((void**)&bthiPtr, g_Bthi);
    __nv_bfloat16* btloPtr = 0;    cudaGetSymbolAddress((void**)&btloPtr, g_Btlo);

    const int GEMM_SMEM = 2 * STAGE_W * 4;
    cudaFuncSetAttribute(gemm_mma_kernel, cudaFuncAttributeMaxDynamicSharedMemorySize,
                         GEMM_SMEM);

    int gE = (e2 + 255) / 256;

    clear_deg_kernel<<<(NNODES + 255) / 256, 256>>>();
    count_deg_kernel<<<gE, 256>>>(dstp, e2);
    scan_kernel<<<1, 1024>>>();
    scatter_kernel<<<gE, 256>>>(src, dstp, e2);

    btsplit_all_kernel<<<dim3(KD * KD / 256, 3), 256>>>(Ws[0], Ws[1], Ws[2]);
    compute_vd_all_kernel<<<3, 1024>>>(Wd[0], Wd[1], Wd[2], Ad[0], Ad[1], Ad[2]);
    prep_x_kernel<<<(NNODES + 7) / 8, 256>>>(x);

    for (int l = 0; l < 3; l++) {
        gemm_mma_kernel<<<dim3(MPAD / 128, 2), 256, GEMM_SMEM>>>(
            As[l], bthiPtr + (size_t)l * KD * KD, btloPtr + (size_t)l * KD * KD);
        if (l < 2)
            aggregate_kernel<<<NNODES, 128>>>(Bb[l], vdPtr + (l + 1) * KD * HEADS,
                                              (float*)0, 0);
        else
            aggregate_kernel<<<NNODES, 128>>>(Bb[l], vdPtr, out, 1);
    }
}

// round 9
// speedup vs baseline: 1.4496x; 1.1374x over previous
#include <cuda_runtime.h>
#include <cuda_bf16.h>
#include <cuda_fp16.h>
#include <math.h>
#include <stdint.h>

#define NNODES 50000
#define MPAD   50048      // 391 * 128
#define KD     256
#define HEADS  4
#define EMAX   1700000

// ---------------- device scratch --------------------------------------------
__device__ __half2         g_hsH[MPAD * KD / 2]; // source transform (fp16)
__device__ __half2         g_Af[MPAD * KD / 2];  // activations, plain fp16
__device__ __half          g_Bthi[3 * KD * KD];  // W^T fp16 split hi, all layers
__device__ __half          g_Btlo[3 * KD * KD];  // W^T fp16 split lo, all layers
__device__ float           g_as[MPAD * HEADS];
__device__ float           g_ad[NNODES * HEADS];
__device__ float           g_vd[3 * KD * HEADS]; // Wd_l @ att_d_l, [l][k][h]
__device__ int             g_deg[NNODES];
__device__ int             g_rowptr[NNODES + 1];
__device__ int             g_cursor[NNODES];
__device__ int             g_srcs[EMAX];         // CSR-ordered SOURCE ids

// ---------------- helpers ----------------------------------------------------
__device__ __forceinline__ void mma_f16(float* c, const uint32_t* a, const uint32_t* b) {
    asm volatile(
        "mma.sync.aligned.m16n8k16.row.col.f32.f16.f16.f32 "
        "{%0,%1,%2,%3},{%4,%5,%6,%7},{%8,%9},{%0,%1,%2,%3};"
        : "+f"(c[0]), "+f"(c[1]), "+f"(c[2]), "+f"(c[3])
        : "r"(a[0]), "r"(a[1]), "r"(a[2]), "r"(a[3]), "r"(b[0]), "r"(b[1]));
}

#define CP_ASYNC16(dst_u32, src_ptr) \
    asm volatile("cp.async.cg.shared.global [%0], [%1], 16;" \
                 :: "r"(dst_u32), "l"(src_ptr))
#define CP_COMMIT() asm volatile("cp.async.commit_group;" ::: "memory")
#define CP_WAIT0()  asm volatile("cp.async.wait_group 0;" ::: "memory")

// ---------------- CSR build (unchanged from R8) ------------------------------
__global__ void clear_deg_kernel() {
    int i = blockIdx.x * blockDim.x + threadIdx.x;
    if (i < NNODES) g_deg[i] = 0;
}
__global__ void count_deg_kernel(const int* __restrict__ dst, int e2) {
    int e = blockIdx.x * blockDim.x + threadIdx.x;
    if (e < e2) atomicAdd(&g_deg[dst[e]], 1);
}
__global__ void scan_kernel() {
    __shared__ int s[1024];
    int t = threadIdx.x;
    const int per = (NNODES + 1023) / 1024;
    int start = t * per;
    int end = start + per; if (end > NNODES) end = NNODES;
    int sum = 0;
    for (int i = start; i < end; i++) sum += g_deg[i];
    s[t] = sum;
    __syncthreads();
    for (int off = 1; off < 1024; off <<= 1) {
        int v = (t >= off) ? s[t - off] : 0;
        __syncthreads();
        s[t] += v;
        __syncthreads();
    }
    int run = (t > 0) ? s[t - 1] : 0;
    for (int i = start; i < end; i++) {
        int d = g_deg[i];
        g_rowptr[i] = run;
        g_cursor[i] = run;
        run += d;
    }
    if (t == 0) g_rowptr[NNODES] = s[1023];
}
__global__ void scatter_kernel(const int* __restrict__ src,
                               const int* __restrict__ dst, int e2) {
    int e = blockIdx.x * blockDim.x + threadIdx.x;
    if (e < e2) {
        int pos = atomicAdd(&g_cursor[dst[e]], 1);
        g_srcs[pos] = src[e];
    }
}

// ---------------- fused: x -> fp16 AND layer-0 a_d ---------------------------
__global__ void __launch_bounds__(256) prep_x_kernel(const float* __restrict__ X) {
    __shared__ float svd[KD * 4];
    int tid = threadIdx.x;
    for (int i = tid; i < KD * 4; i += 256) svd[i] = g_vd[i];
    __syncthreads();
    int warp = tid >> 5, lane = tid & 31;
    int n = blockIdx.x * 8 + warp;
    if (n >= NNODES) return;
    float a0 = 0.f, a1 = 0.f, a2 = 0.f, a3 = 0.f;
#pragma unroll
    for (int g4 = 0; g4 < 2; g4++) {
        int f4i = n * 64 + lane * 2 + g4;
        float4 xv = ((const float4*)X)[f4i];
        __half2 h01 = __floats2half2_rn(xv.x, xv.y);
        __half2 h23 = __floats2half2_rn(xv.z, xv.w);
        uint2 hp;
        hp.x = *reinterpret_cast<unsigned*>(&h01);
        hp.y = *reinterpret_cast<unsigned*>(&h23);
        ((uint2*)g_Af)[f4i] = hp;
        const float* p = &svd[(lane * 8 + g4 * 4) * 4];
        a0 += xv.x * p[0] + xv.y * p[4] + xv.z * p[8]  + xv.w * p[12];
        a1 += xv.x * p[1] + xv.y * p[5] + xv.z * p[9]  + xv.w * p[13];
        a2 += xv.x * p[2] + xv.y * p[6] + xv.z * p[10] + xv.w * p[14];
        a3 += xv.x * p[3] + xv.y * p[7] + xv.z * p[11] + xv.w * p[15];
    }
#pragma unroll
    for (int off = 16; off > 0; off >>= 1) {
        a0 += __shfl_xor_sync(0xffffffffu, a0, off);
        a1 += __shfl_xor_sync(0xffffffffu, a1, off);
        a2 += __shfl_xor_sync(0xffffffffu, a2, off);
        a3 += __shfl_xor_sync(0xffffffffu, a3, off);
    }
    if (lane == 0) ((float4*)g_ad)[n] = make_float4(a0, a1, a2, a3);
}

// ---------------- B transpose + fp16 split, all 3 layers ---------------------
__global__ void btsplit_all_kernel(const float* __restrict__ W0,
                                   const float* __restrict__ W1,
                                   const float* __restrict__ W2) {
    int l = blockIdx.y;
    const float* W = (l == 0) ? W0 : (l == 1) ? W1 : W2;
    int i = blockIdx.x * blockDim.x + threadIdx.x;
    int n = i >> 8, k = i & 255;
    float v = W[k * KD + n];
    __half h = __float2half_rn(v);
    g_Bthi[l * KD * KD + i] = h;
    g_Btlo[l * KD * KD + i] = __float2half_rn(v - __half2float(h));
}

// ---------------- vd for all layers in one launch ----------------------------
__global__ void compute_vd_all_kernel(const float* __restrict__ Wd0,
                                      const float* __restrict__ Wd1,
                                      const float* __restrict__ Wd2,
                                      const float* __restrict__ ad0,
                                      const float* __restrict__ ad1,
                                      const float* __restrict__ ad2) {
    int l = blockIdx.x;
    const float* Wd = (l == 0) ? Wd0 : (l == 1) ? Wd1 : Wd2;
    const float* ad = (l == 0) ? ad0 : (l == 1) ? ad1 : ad2;
    int idx = threadIdx.x;
    int k = idx >> 2;
    int h = idx & 3;
    float s = 0.f;
#pragma unroll 8
    for (int c = 0; c < 64; c++) s += Wd[k * KD + h * 64 + c] * ad[h * 64 + c];
    g_vd[l * KD * HEADS + k * 4 + h] = s;
}

// ---------------- GEMM: hs(fp16) = A(fp16) @ (Bh+Bl), 2 products -------------
// grid (391, 2), 256 threads. CTA tile 128x128, BK=32, cp.async 2-stage.
#define S32 20
#define STAGE_W 7680         // words per stage: 3 arrays * 128*20
__global__ void __launch_bounds__(256) gemm_mma_kernel(const float* __restrict__ attS,
                                                       const __half* __restrict__ Bh,
                                                       const __half* __restrict__ Bl) {
    extern __shared__ uint32_t smem_u[];
    __shared__ float s_as[128][2];
    const int tid = threadIdx.x;
    const int wid = tid >> 5, lane = tid & 31;
    const int wm = wid >> 2, wn = wid & 3;
    const int row0 = blockIdx.x * 128;
    const int n0 = blockIdx.y * 128;
    const int g8 = lane >> 2, tq = lane & 3;
    const uint32_t smem_b = (uint32_t)__cvta_generic_to_shared(smem_u);
    const __half* Af = (const __half*)g_Af;

    ((float*)s_as)[tid] = 0.f;

    const int lr0 = tid >> 2;
    const int lc4 = tid & 3;
    float c[4][4][4];
#pragma unroll
    for (int mt = 0; mt < 4; mt++)
#pragma unroll
        for (int nt = 0; nt < 4; nt++)
#pragma unroll
            for (int j = 0; j < 4; j++) c[mt][nt][j] = 0.f;

#define LOAD_CHUNK(stg, cc) do {                                               \
    int k0 = (cc) * 32;                                                        \
    _Pragma("unroll")                                                          \
    for (int i = 0; i < 2; i++) {                                              \
        int r = lr0 + i * 64;                                                  \
        long ga = (long)(row0 + r) * KD + k0 + lc4 * 8;                        \
        long gb = (long)(n0 + r) * KD + k0 + lc4 * 8;                          \
        uint32_t so = smem_b + ((stg) * STAGE_W + r * S32 + lc4 * 4) * 4;      \
        CP_ASYNC16(so,            Af + ga);                                    \
        CP_ASYNC16(so + 2560 * 4, Bh + gb);                                    \
        CP_ASYNC16(so + 5120 * 4, Bl + gb);                                    \
    }                                                                          \
} while (0)

    LOAD_CHUNK(0, 0);
    CP_COMMIT();

    for (int cch = 0; cch < 8; cch++) {
        const int stg = cch & 1;
        CP_WAIT0();
        __syncthreads();
        if (cch < 7) { LOAD_CHUNK(stg ^ 1, cch + 1); CP_COMMIT(); }
        const uint32_t* sA  = smem_u + stg * STAGE_W;
        const uint32_t* sBh = sA + 2560;
        const uint32_t* sBl = sA + 5120;
#pragma unroll
        for (int kk = 0; kk < 2; kk++) {
            const int kb = kk * 8;
            uint32_t ah[4][4], bh[4][2], bl[4][2];
#pragma unroll
            for (int mt = 0; mt < 4; mt++) {
                int r = (wm * 64 + mt * 16 + g8) * S32 + kb + tq;
                int r8 = r + 8 * S32;
                ah[mt][0] = sA[r];     ah[mt][1] = sA[r8];
                ah[mt][2] = sA[r + 4]; ah[mt][3] = sA[r8 + 4];
            }
#pragma unroll
            for (int nt = 0; nt < 4; nt++) {
                int r = (wn * 32 + nt * 8 + g8) * S32 + kb + tq;
                bh[nt][0] = sBh[r]; bh[nt][1] = sBh[r + 4];
                bl[nt][0] = sBl[r]; bl[nt][1] = sBl[r + 4];
            }
#pragma unroll
            for (int mt = 0; mt < 4; mt++)
#pragma unroll
                for (int nt = 0; nt < 4; nt++) {
                    mma_f16(c[mt][nt], ah[mt], bh[nt]);
                    mma_f16(c[mt][nt], ah[mt], bl[nt]);
                }
        }
        __syncthreads();
    }

    // epilogue 1: fragments -> g_hsH (fp16)
#pragma unroll
    for (int mt = 0; mt < 4; mt++) {
        int r = row0 + wm * 64 + mt * 16 + g8;
#pragma unroll
        for (int nt = 0; nt < 4; nt++) {
            int h2i = 64 * blockIdx.y + wn * 16 + nt * 4 + tq;
            g_hsH[(long)r * 128 + h2i]       = __floats2half2_rn(c[mt][nt][0], c[mt][nt][1]);
            g_hsH[(long)(r + 8) * 128 + h2i] = __floats2half2_rn(c[mt][nt][2], c[mt][nt][3]);
        }
    }
    // epilogue 2: fused a_s via block-shared reduction
    {
        float p0[4] = {0.f, 0.f, 0.f, 0.f};
        float p1[4] = {0.f, 0.f, 0.f, 0.f};
#pragma unroll
        for (int nt = 0; nt < 4; nt++) {
            int col = n0 + wn * 32 + nt * 8 + tq * 2;
            float a0 = attS[col], a1 = attS[col + 1];
#pragma unroll
            for (int mt = 0; mt < 4; mt++) {
                p0[mt] += c[mt][nt][0] * a0 + c[mt][nt][1] * a1;
                p1[mt] += c[mt][nt][2] * a0 + c[mt][nt][3] * a1;
            }
        }
        int hl = wn >> 1;
#pragma unroll
        for (int mt = 0; mt < 4; mt++) {
            p0[mt] += __shfl_xor_sync(0xffffffffu, p0[mt], 1);
            p0[mt] += __shfl_xor_sync(0xffffffffu, p0[mt], 2);
            p1[mt] += __shfl_xor_sync(0xffffffffu, p1[mt], 1);
            p1[mt] += __shfl_xor_sync(0xffffffffu, p1[mt], 2);
            if (tq == 0) {
                int rl = wm * 64 + mt * 16 + g8;
                atomicAdd(&s_as[rl][hl], p0[mt]);
                atomicAdd(&s_as[rl + 8][hl], p1[mt]);
            }
        }
        __syncthreads();
        int rl = tid >> 1, h2 = tid & 1;
        g_as[(row0 + rl) * 4 + blockIdx.y * 2 + h2] = s_as[rl][h2];
    }
}

// ---------------- aggregation: R8 structure, fp16 in & out -------------------
__global__ void __launch_bounds__(128) aggregate_kernel(const float* __restrict__ bias,
                                                        const float* __restrict__ vdn,
                                                        float* __restrict__ out,
                                                        int mode) {
    __shared__ float s_ex[4][64];
    __shared__ int   s_si[4][64];
    __shared__ float s_adp[4][4];
    __shared__ float sh[256];
    __shared__ float s_red[2];

    const int n = blockIdx.x;
    const int tid = threadIdx.x;
    const int w = tid >> 5, lane = tid & 31;
    const int base = g_rowptr[n];
    const int deg = g_rowptr[n + 1] - base;

    const float adw = g_ad[n * 4 + w];
    const __half2* __restrict__ hs2 = g_hsH;
    const int colIdx = w * 32 + lane;

    float a0x = 0.f, a0y = 0.f, a1x = 0.f, a1y = 0.f;
    float exsum = 0.f;
    for (int cs = 0; cs < deg; cs += 64) {
        int m = deg - cs; if (m > 64) m = 64;
        if (lane < m) {
            int sI = g_srcs[base + cs + lane];
            float al = g_as[sI * 4 + w] + adw;
            al = al > 0.f ? al : 0.2f * al;
            float ex = __expf(al);
            exsum += ex;
            s_ex[w][lane] = ex;
            s_si[w][lane] = sI;
        }
        if (lane + 32 < m) {
            int sI = g_srcs[base + cs + lane + 32];
            float al = g_as[sI * 4 + w] + adw;
            al = al > 0.f ? al : 0.2f * al;
            float ex = __expf(al);
            exsum += ex;
            s_ex[w][lane + 32] = ex;
            s_si[w][lane + 32] = sI;
        }
        __syncwarp();
        int j = 0;
        for (; j + 8 <= m; j += 8) {
#pragma unroll
            for (int u = 0; u < 8; u += 2) {
                float e0 = s_ex[w][j + u];     int s0 = s_si[w][j + u];
                float e1 = s_ex[w][j + u + 1]; int s1 = s_si[w][j + u + 1];
                float2 h0 = __half22float2(hs2[(long)s0 * 128 + colIdx]);
                float2 h1 = __half22float2(hs2[(long)s1 * 128 + colIdx]);
                a0x += e0 * h0.x; a0y += e0 * h0.y;
                a1x += e1 * h1.x; a1y += e1 * h1.y;
            }
        }
        for (; j < m; j++) {
            float e0 = s_ex[w][j]; int s0 = s_si[w][j];
            float2 h0 = __half22float2(hs2[(long)s0 * 128 + colIdx]);
            a0x += e0 * h0.x; a0y += e0 * h0.y;
        }
        __syncwarp();
    }
#pragma unroll
    for (int off = 16; off > 0; off >>= 1)
        exsum += __shfl_xor_sync(0xffffffffu, exsum, off);
    const float den = exsum + 1e-16f;

    const int col0 = w * 64 + lane * 2;
    float v0 = (a0x + a1x) / den;
    float v1 = (a0y + a1y) / den;
    if (mode == 0) {
        v0 += bias[col0];
        v1 += bias[col0 + 1];
        v0 = v0 > 0.f ? v0 : expm1f(v0);
        v1 = v1 > 0.f ? v1 : expm1f(v1);
        g_Af[(long)n * 128 + colIdx] = __floats2half2_rn(v0, v1);
        const float* p0 = &vdn[col0 * 4];
        float q0 = v0 * p0[0] + v1 * p0[4];
        float q1 = v0 * p0[1] + v1 * p0[5];
        float q2 = v0 * p0[2] + v1 * p0[6];
        float q3 = v0 * p0[3] + v1 * p0[7];
#pragma unroll
        for (int off = 16; off > 0; off >>= 1) {
            q0 += __shfl_xor_sync(0xffffffffu, q0, off);
            q1 += __shfl_xor_sync(0xffffffffu, q1, off);
            q2 += __shfl_xor_sync(0xffffffffu, q2, off);
            q3 += __shfl_xor_sync(0xffffffffu, q3, off);
        }
        if (lane < 4) {
            float q = lane == 0 ? q0 : lane == 1 ? q1 : lane == 2 ? q2 : q3;
            s_adp[w][lane] = q;
        }
        __syncthreads();
        if (tid < 4)
            g_ad[n * 4 + tid] = s_adp[0][tid] + s_adp[1][tid] + s_adp[2][tid] + s_adp[3][tid];
    } else {
        sh[col0] = v0;
        sh[col0 + 1] = v1;
        __syncthreads();
        if (tid < 64)
            sh[tid] = 0.25f * (sh[tid] + sh[tid + 64] + sh[tid + 128] + sh[tid + 192]) + bias[tid];
        __syncthreads();
        if (tid < 32) {
            float a = fmaxf(sh[tid], sh[tid + 32]);
#pragma unroll
            for (int off = 16; off > 0; off >>= 1)
                a = fmaxf(a, __shfl_xor_sync(0xffffffffu, a, off));
            if (tid == 0) s_red[0] = a;
        }
        __syncthreads();
        if (tid < 32) {
            float mx = s_red[0];
            float a = expf(sh[tid] - mx) + expf(sh[tid + 32] - mx);
#pragma unroll
            for (int off = 16; off > 0; off >>= 1)
                a += __shfl_xor_sync(0xffffffffu, a, off);
            if (tid == 0) s_red[1] = a;
        }
        __syncthreads();
        if (tid < 64) out[(long)n * 64 + tid] = sh[tid] - s_red[0] - logf(s_red[1]);
    }
}

// ---------------- launch -----------------------------------------------------
extern "C" void kernel_launch(void* const* d_in, const int* in_sizes, int n_in,
                              void* d_out, int out_size) {
    const float* x = (const float*)d_in[0];
    const int* ei = (const int*)d_in[1];
    int e2 = in_sizes[1] / 2;
    const int* src = ei;
    const int* dstp = ei + e2;
    const float* Ws[3] = {(const float*)d_in[2], (const float*)d_in[7],  (const float*)d_in[12]};
    const float* Wd[3] = {(const float*)d_in[3], (const float*)d_in[8],  (const float*)d_in[13]};
    const float* As[3] = {(const float*)d_in[4], (const float*)d_in[9],  (const float*)d_in[14]};
    const float* Ad[3] = {(const float*)d_in[5], (const float*)d_in[10], (const float*)d_in[15]};
    const float* Bb[3] = {(const float*)d_in[6], (const float*)d_in[11], (const float*)d_in[16]};
    float* out = (float*)d_out;

    float* vdPtr = 0;      cudaGetSymbolAddress((void**)&vdPtr, g_vd);
    __half* bthiPtr = 0;   cudaGetSymbolAddress((void**)&bthiPtr, g_Bthi);
    __half* btloPtr = 0;   cudaGetSymbolAddress((void**)&btloPtr, g_Btlo);

    const int GEMM_SMEM = 2 * STAGE_W * 4;   // 61440 B
    cudaFuncSetAttribute(gemm_mma_kernel, cudaFuncAttributeMaxDynamicSharedMemorySize,
                         GEMM_SMEM);

    int gE = (e2 + 255) / 256;

    clear_deg_kernel<<<(NNODES + 255) / 256, 256>>>();
    count_deg_kernel<<<gE, 256>>>(dstp, e2);
    scan_kernel<<<1, 1024>>>();
    scatter_kernel<<<gE, 256>>>(src, dstp, e2);

    btsplit_all_kernel<<<dim3(KD * KD / 256, 3), 256>>>(Ws[0], Ws[1], Ws[2]);
    compute_vd_all_kernel<<<3, 1024>>>(Wd[0], Wd[1], Wd[2], Ad[0], Ad[1], Ad[2]);
    prep_x_kernel<<<(NNODES + 7) / 8, 256>>>(x);

    for (int l = 0; l < 3; l++) {
        gemm_mma_kernel<<<dim3(MPAD / 128, 2), 256, GEMM_SMEM>>>(
            As[l], bthiPtr + (size_t)l * KD * KD, btloPtr + (size_t)l * KD * KD);
        if (l < 2)
            aggregate_kernel<<<NNODES, 128>>>(Bb[l], vdPtr + (l + 1) * KD * HEADS,
                                              (float*)0, 0);
        else
            aggregate_kernel<<<NNODES, 128>>>(Bb[l], vdPtr, out, 1);
    }
}

// round 10
// speedup vs baseline: 1.5157x; 1.0457x over previous
#include <cuda_runtime.h>
#include <cuda_bf16.h>
#include <cuda_fp16.h>
#include <math.h>
#include <stdint.h>

#define NNODES 50000
#define MPAD   50048      // 391 * 128
#define KD     256
#define HEADS  4
#define EMAX   1700000

// ---------------- device scratch --------------------------------------------
__device__ __half2         g_hsH[MPAD * KD / 2]; // source transform (fp16)
__device__ __half2         g_Af[MPAD * KD / 2];  // activations, plain fp16
__device__ __half          g_Bt[3 * KD * KD];    // W^T fp16, all layers
__device__ float           g_as[MPAD * HEADS];
__device__ float           g_ad[NNODES * HEADS];
__device__ float           g_vd[3 * KD * HEADS]; // Wd_l @ att_d_l, [l][k][h]
__device__ int             g_deg[NNODES];
__device__ int             g_rowptr[NNODES + 1];
__device__ int             g_cursor[NNODES];
__device__ int             g_srcs[EMAX];         // CSR-ordered SOURCE ids

// ---------------- helpers ----------------------------------------------------
__device__ __forceinline__ void mma_f16(float* c, const uint32_t* a, const uint32_t* b) {
    asm volatile(
        "mma.sync.aligned.m16n8k16.row.col.f32.f16.f16.f32 "
        "{%0,%1,%2,%3},{%4,%5,%6,%7},{%8,%9},{%0,%1,%2,%3};"
        : "+f"(c[0]), "+f"(c[1]), "+f"(c[2]), "+f"(c[3])
        : "r"(a[0]), "r"(a[1]), "r"(a[2]), "r"(a[3]), "r"(b[0]), "r"(b[1]));
}

#define CP_ASYNC16(dst_u32, src_ptr) \
    asm volatile("cp.async.cg.shared.global [%0], [%1], 16;" \
                 :: "r"(dst_u32), "l"(src_ptr))
#define CP_COMMIT() asm volatile("cp.async.commit_group;" ::: "memory")
#define CP_WAIT0()  asm volatile("cp.async.wait_group 0;" ::: "memory")

// ---------------- CSR build (unchanged) --------------------------------------
__global__ void clear_deg_kernel() {
    int i = blockIdx.x * blockDim.x + threadIdx.x;
    if (i < NNODES) g_deg[i] = 0;
}
__global__ void count_deg_kernel(const int* __restrict__ dst, int e2) {
    int e = blockIdx.x * blockDim.x + threadIdx.x;
    if (e < e2) atomicAdd(&g_deg[dst[e]], 1);
}
__global__ void scan_kernel() {
    __shared__ int s[1024];
    int t = threadIdx.x;
    const int per = (NNODES + 1023) / 1024;
    int start = t * per;
    int end = start + per; if (end > NNODES) end = NNODES;
    int sum = 0;
    for (int i = start; i < end; i++) sum += g_deg[i];
    s[t] = sum;
    __syncthreads();
    for (int off = 1; off < 1024; off <<= 1) {
        int v = (t >= off) ? s[t - off] : 0;
        __syncthreads();
        s[t] += v;
        __syncthreads();
    }
    int run = (t > 0) ? s[t - 1] : 0;
    for (int i = start; i < end; i++) {
        int d = g_deg[i];
        g_rowptr[i] = run;
        g_cursor[i] = run;
        run += d;
    }
    if (t == 0) g_rowptr[NNODES] = s[1023];
}
__global__ void scatter_kernel(const int* __restrict__ src,
                               const int* __restrict__ dst, int e2) {
    int e = blockIdx.x * blockDim.x + threadIdx.x;
    if (e < e2) {
        int pos = atomicAdd(&g_cursor[dst[e]], 1);
        g_srcs[pos] = src[e];
    }
}

// ---------------- fused: x -> fp16 AND layer-0 a_d ---------------------------
__global__ void __launch_bounds__(256) prep_x_kernel(const float* __restrict__ X) {
    __shared__ float svd[KD * 4];
    int tid = threadIdx.x;
    for (int i = tid; i < KD * 4; i += 256) svd[i] = g_vd[i];
    __syncthreads();
    int warp = tid >> 5, lane = tid & 31;
    int n = blockIdx.x * 8 + warp;
    if (n >= NNODES) return;
    float a0 = 0.f, a1 = 0.f, a2 = 0.f, a3 = 0.f;
#pragma unroll
    for (int g4 = 0; g4 < 2; g4++) {
        int f4i = n * 64 + lane * 2 + g4;
        float4 xv = ((const float4*)X)[f4i];
        __half2 h01 = __floats2half2_rn(xv.x, xv.y);
        __half2 h23 = __floats2half2_rn(xv.z, xv.w);
        uint2 hp;
        hp.x = *reinterpret_cast<unsigned*>(&h01);
        hp.y = *reinterpret_cast<unsigned*>(&h23);
        ((uint2*)g_Af)[f4i] = hp;
        const float* p = &svd[(lane * 8 + g4 * 4) * 4];
        a0 += xv.x * p[0] + xv.y * p[4] + xv.z * p[8]  + xv.w * p[12];
        a1 += xv.x * p[1] + xv.y * p[5] + xv.z * p[9]  + xv.w * p[13];
        a2 += xv.x * p[2] + xv.y * p[6] + xv.z * p[10] + xv.w * p[14];
        a3 += xv.x * p[3] + xv.y * p[7] + xv.z * p[11] + xv.w * p[15];
    }
#pragma unroll
    for (int off = 16; off > 0; off >>= 1) {
        a0 += __shfl_xor_sync(0xffffffffu, a0, off);
        a1 += __shfl_xor_sync(0xffffffffu, a1, off);
        a2 += __shfl_xor_sync(0xffffffffu, a2, off);
        a3 += __shfl_xor_sync(0xffffffffu, a3, off);
    }
    if (lane == 0) ((float4*)g_ad)[n] = make_float4(a0, a1, a2, a3);
}

// ---------------- B transpose -> fp16, all 3 layers --------------------------
__global__ void btsplit_all_kernel(const float* __restrict__ W0,
                                   const float* __restrict__ W1,
                                   const float* __restrict__ W2) {
    int l = blockIdx.y;
    const float* W = (l == 0) ? W0 : (l == 1) ? W1 : W2;
    int i = blockIdx.x * blockDim.x + threadIdx.x;
    int n = i >> 8, k = i & 255;
    g_Bt[l * KD * KD + i] = __float2half_rn(W[k * KD + n]);
}

// ---------------- vd for all layers in one launch ----------------------------
__global__ void compute_vd_all_kernel(const float* __restrict__ Wd0,
                                      const float* __restrict__ Wd1,
                                      const float* __restrict__ Wd2,
                                      const float* __restrict__ ad0,
                                      const float* __restrict__ ad1,
                                      const float* __restrict__ ad2) {
    int l = blockIdx.x;
    const float* Wd = (l == 0) ? Wd0 : (l == 1) ? Wd1 : Wd2;
    const float* ad = (l == 0) ? ad0 : (l == 1) ? ad1 : ad2;
    int idx = threadIdx.x;
    int k = idx >> 2;
    int h = idx & 3;
    float s = 0.f;
#pragma unroll 8
    for (int c = 0; c < 64; c++) s += Wd[k * KD + h * 64 + c] * ad[h * 64 + c];
    g_vd[l * KD * HEADS + k * 4 + h] = s;
}

// ---------------- GEMM: hs(fp16) = A(fp16) @ B(fp16), single product ---------
// grid (391, 2), 256 threads. CTA tile 128x128, BK=32, cp.async 2-stage.
#define S32 20
#define STAGE_W 5120         // words per stage: 2 arrays * 128*20
__global__ void __launch_bounds__(256) gemm_mma_kernel(const float* __restrict__ attS,
                                                       const __half* __restrict__ Bh) {
    extern __shared__ uint32_t smem_u[];
    __shared__ float s_as[128][2];
    const int tid = threadIdx.x;
    const int wid = tid >> 5, lane = tid & 31;
    const int wm = wid >> 2, wn = wid & 3;
    const int row0 = blockIdx.x * 128;
    const int n0 = blockIdx.y * 128;
    const int g8 = lane >> 2, tq = lane & 3;
    const uint32_t smem_b = (uint32_t)__cvta_generic_to_shared(smem_u);
    const __half* Af = (const __half*)g_Af;

    ((float*)s_as)[tid] = 0.f;

    const int lr0 = tid >> 2;
    const int lc4 = tid & 3;
    float c[4][4][4];
#pragma unroll
    for (int mt = 0; mt < 4; mt++)
#pragma unroll
        for (int nt = 0; nt < 4; nt++)
#pragma unroll
            for (int j = 0; j < 4; j++) c[mt][nt][j] = 0.f;

#define LOAD_CHUNK(stg, cc) do {                                               \
    int k0 = (cc) * 32;                                                        \
    _Pragma("unroll")                                                          \
    for (int i = 0; i < 2; i++) {                                              \
        int r = lr0 + i * 64;                                                  \
        long ga = (long)(row0 + r) * KD + k0 + lc4 * 8;                        \
        long gb = (long)(n0 + r) * KD + k0 + lc4 * 8;                          \
        uint32_t so = smem_b + ((stg) * STAGE_W + r * S32 + lc4 * 4) * 4;      \
        CP_ASYNC16(so,            Af + ga);                                    \
        CP_ASYNC16(so + 2560 * 4, Bh + gb);                                    \
    }                                                                          \
} while (0)

    LOAD_CHUNK(0, 0);
    CP_COMMIT();

    for (int cch = 0; cch < 8; cch++) {
        const int stg = cch & 1;
        CP_WAIT0();
        __syncthreads();
        if (cch < 7) { LOAD_CHUNK(stg ^ 1, cch + 1); CP_COMMIT(); }
        const uint32_t* sA  = smem_u + stg * STAGE_W;
        const uint32_t* sBh = sA + 2560;
#pragma unroll
        for (int kk = 0; kk < 2; kk++) {
            const int kb = kk * 8;
            uint32_t ah[4][4], bh[4][2];
#pragma unroll
            for (int mt = 0; mt < 4; mt++) {
                int r = (wm * 64 + mt * 16 + g8) * S32 + kb + tq;
                int r8 = r + 8 * S32;
                ah[mt][0] = sA[r];     ah[mt][1] = sA[r8];
                ah[mt][2] = sA[r + 4]; ah[mt][3] = sA[r8 + 4];
            }
#pragma unroll
            for (int nt = 0; nt < 4; nt++) {
                int r = (wn * 32 + nt * 8 + g8) * S32 + kb + tq;
                bh[nt][0] = sBh[r]; bh[nt][1] = sBh[r + 4];
            }
#pragma unroll
            for (int mt = 0; mt < 4; mt++)
#pragma unroll
                for (int nt = 0; nt < 4; nt++)
                    mma_f16(c[mt][nt], ah[mt], bh[nt]);
        }
        __syncthreads();
    }

    // epilogue 1: fragments -> g_hsH (fp16)
#pragma unroll
    for (int mt = 0; mt < 4; mt++) {
        int r = row0 + wm * 64 + mt * 16 + g8;
#pragma unroll
        for (int nt = 0; nt < 4; nt++) {
            int h2i = 64 * blockIdx.y + wn * 16 + nt * 4 + tq;
            g_hsH[(long)r * 128 + h2i]       = __floats2half2_rn(c[mt][nt][0], c[mt][nt][1]);
            g_hsH[(long)(r + 8) * 128 + h2i] = __floats2half2_rn(c[mt][nt][2], c[mt][nt][3]);
        }
    }
    // epilogue 2: fused a_s via block-shared reduction
    {
        float p0[4] = {0.f, 0.f, 0.f, 0.f};
        float p1[4] = {0.f, 0.f, 0.f, 0.f};
#pragma unroll
        for (int nt = 0; nt < 4; nt++) {
            int col = n0 + wn * 32 + nt * 8 + tq * 2;
            float a0 = attS[col], a1 = attS[col + 1];
#pragma unroll
            for (int mt = 0; mt < 4; mt++) {
                p0[mt] += c[mt][nt][0] * a0 + c[mt][nt][1] * a1;
                p1[mt] += c[mt][nt][2] * a0 + c[mt][nt][3] * a1;
            }
        }
        int hl = wn >> 1;
#pragma unroll
        for (int mt = 0; mt < 4; mt++) {
            p0[mt] += __shfl_xor_sync(0xffffffffu, p0[mt], 1);
            p0[mt] += __shfl_xor_sync(0xffffffffu, p0[mt], 2);
            p1[mt] += __shfl_xor_sync(0xffffffffu, p1[mt], 1);
            p1[mt] += __shfl_xor_sync(0xffffffffu, p1[mt], 2);
            if (tq == 0) {
                int rl = wm * 64 + mt * 16 + g8;
                atomicAdd(&s_as[rl][hl], p0[mt]);
                atomicAdd(&s_as[rl + 8][hl], p1[mt]);
            }
        }
        __syncthreads();
        int rl = tid >> 1, h2 = tid & 1;
        g_as[(row0 + rl) * 4 + blockIdx.y * 2 + h2] = s_as[rl][h2];
    }
}

// ---------------- aggregation: block-staged edges (dedup src/as loads) -------
// Threads 0..63 stage one edge each (srcs + a_s float4 + all 4 exps), then
// warp w gathers its head's 64 columns. exsum is lane-uniform (no reduce).
__global__ void __launch_bounds__(128) aggregate_kernel(const float* __restrict__ bias,
                                                        const float* __restrict__ vdn,
                                                        float* __restrict__ out,
                                                        int mode) {
    __shared__ float s_ex[64][4];
    __shared__ int   s_si[64];
    __shared__ float s_adp[4][4];
    __shared__ float sh[256];
    __shared__ float s_red[2];

    const int n = blockIdx.x;
    const int tid = threadIdx.x;
    const int w = tid >> 5, lane = tid & 31;
    const int base = g_rowptr[n];
    const int deg = g_rowptr[n + 1] - base;

    float4 ad4 = make_float4(0.f, 0.f, 0.f, 0.f);
    if (tid < 64) ad4 = ((const float4*)g_ad)[n];

    const __half2* __restrict__ hs2 = g_hsH;
    const int colIdx = w * 32 + lane;

    float a0x = 0.f, a0y = 0.f, a1x = 0.f, a1y = 0.f;
    float exsum = 0.f;
    for (int cs = 0; cs < deg; cs += 64) {
        int m = deg - cs; if (m > 64) m = 64;
        if (tid < m) {
            int sI = g_srcs[base + cs + tid];
            float4 a = ((const float4*)g_as)[sI];
            float v; float4 ex;
            v = a.x + ad4.x; v = v > 0.f ? v : 0.2f * v; ex.x = __expf(v);
            v = a.y + ad4.y; v = v > 0.f ? v : 0.2f * v; ex.y = __expf(v);
            v = a.z + ad4.z; v = v > 0.f ? v : 0.2f * v; ex.z = __expf(v);
            v = a.w + ad4.w; v = v > 0.f ? v : 0.2f * v; ex.w = __expf(v);
            *(float4*)s_ex[tid] = ex;
            s_si[tid] = sI;
        }
        __syncthreads();
        int j = 0;
        for (; j + 8 <= m; j += 8) {
#pragma unroll
            for (int u = 0; u < 8; u += 2) {
                float e0 = s_ex[j + u][w];     int s0 = s_si[j + u];
                float e1 = s_ex[j + u + 1][w]; int s1 = s_si[j + u + 1];
                float2 h0 = __half22float2(hs2[(long)s0 * 128 + colIdx]);
                float2 h1 = __half22float2(hs2[(long)s1 * 128 + colIdx]);
                a0x += e0 * h0.x; a0y += e0 * h0.y;
                a1x += e1 * h1.x; a1y += e1 * h1.y;
                exsum += e0 + e1;
            }
        }
        for (; j < m; j++) {
            float e0 = s_ex[j][w]; int s0 = s_si[j];
            float2 h0 = __half22float2(hs2[(long)s0 * 128 + colIdx]);
            a0x += e0 * h0.x; a0y += e0 * h0.y;
            exsum += e0;
        }
        __syncthreads();
    }
    const float den = exsum + 1e-16f;   // lane-uniform: staged exps are shared

    const int col0 = w * 64 + lane * 2;
    float v0 = (a0x + a1x) / den;
    float v1 = (a0y + a1y) / den;
    if (mode == 0) {
        v0 += bias[col0];
        v1 += bias[col0 + 1];
        v0 = v0 > 0.f ? v0 : expm1f(v0);
        v1 = v1 > 0.f ? v1 : expm1f(v1);
        g_Af[(long)n * 128 + colIdx] = __floats2half2_rn(v0, v1);
        const float* p0 = &vdn[col0 * 4];
        float q0 = v0 * p0[0] + v1 * p0[4];
        float q1 = v0 * p0[1] + v1 * p0[5];
        float q2 = v0 * p0[2] + v1 * p0[6];
        float q3 = v0 * p0[3] + v1 * p0[7];
#pragma unroll
        for (int off = 16; off > 0; off >>= 1) {
            q0 += __shfl_xor_sync(0xffffffffu, q0, off);
            q1 += __shfl_xor_sync(0xffffffffu, q1, off);
            q2 += __shfl_xor_sync(0xffffffffu, q2, off);
            q3 += __shfl_xor_sync(0xffffffffu, q3, off);
        }
        if (lane < 4) {
            float q = lane == 0 ? q0 : lane == 1 ? q1 : lane == 2 ? q2 : q3;
            s_adp[w][lane] = q;
        }
        __syncthreads();
        if (tid < 4)
            g_ad[n * 4 + tid] = s_adp[0][tid] + s_adp[1][tid] + s_adp[2][tid] + s_adp[3][tid];
    } else {
        sh[col0] = v0;
        sh[col0 + 1] = v1;
        __syncthreads();
        if (tid < 64)
            sh[tid] = 0.25f * (sh[tid] + sh[tid + 64] + sh[tid + 128] + sh[tid + 192]) + bias[tid];
        __syncthreads();
        if (tid < 32) {
            float a = fmaxf(sh[tid], sh[tid + 32]);
#pragma unroll
            for (int off = 16; off > 0; off >>= 1)
                a = fmaxf(a, __shfl_xor_sync(0xffffffffu, a, off));
            if (tid == 0) s_red[0] = a;
        }
        __syncthreads();
        if (tid < 32) {
            float mx = s_red[0];
            float a = expf(sh[tid] - mx) + expf(sh[tid + 32] - mx);
#pragma unroll
            for (int off = 16; off > 0; off >>= 1)
                a += __shfl_xor_sync(0xffffffffu, a, off);
            if (tid == 0) s_red[1] = a;
        }
        __syncthreads();
        if (tid < 64) out[(long)n * 64 + tid] = sh[tid] - s_red[0] - logf(s_red[1]);
    }
}

// ---------------- launch -----------------------------------------------------
extern "C" void kernel_launch(void* const* d_in, const int* in_sizes, int n_in,
                              void* d_out, int out_size) {
    const float* x = (const float*)d_in[0];
    const int* ei = (const int*)d_in[1];
    int e2 = in_sizes[1] / 2;
    const int* src = ei;
    const int* dstp = ei + e2;
    const float* Ws[3] = {(const float*)d_in[2], (const float*)d_in[7],  (const float*)d_in[12]};
    const float* Wd[3] = {(const float*)d_in[3], (const float*)d_in[8],  (const float*)d_in[13]};
    const float* As[3] = {(const float*)d_in[4], (const float*)d_in[9],  (const float*)d_in[14]};
    const float* Ad[3] = {(const float*)d_in[5], (const float*)d_in[10], (const float*)d_in[15]};
    const float* Bb[3] = {(const float*)d_in[6], (const float*)d_in[11], (const float*)d_in[16]};
    float* out = (float*)d_out;

    float* vdPtr = 0;      cudaGetSymbolAddress((void**)&vdPtr, g_vd);
    __half* btPtr = 0;     cudaGetSymbolAddress((void**)&btPtr, g_Bt);

    const int GEMM_SMEM = 2 * STAGE_W * 4;   // 40960 B
    cudaFuncSetAttribute(gemm_mma_kernel, cudaFuncAttributeMaxDynamicSharedMemorySize,
                         GEMM_SMEM);

    int gE = (e2 + 255) / 256;

    clear_deg_kernel<<<(NNODES + 255) / 256, 256>>>();
    count_deg_kernel<<<gE, 256>>>(dstp, e2);
    scan_kernel<<<1, 1024>>>();
    scatter_kernel<<<gE, 256>>>(src, dstp, e2);

    btsplit_all_kernel<<<dim3(KD * KD / 256, 3), 256>>>(Ws[0], Ws[1], Ws[2]);
    compute_vd_all_kernel<<<3, 1024>>>(Wd[0], Wd[1], Wd[2], Ad[0], Ad[1], Ad[2]);
    prep_x_kernel<<<(NNODES + 7) / 8, 256>>>(x);

    for (int l = 0; l < 3; l++) {
        gemm_mma_kernel<<<dim3(MPAD / 128, 2), 256, GEMM_SMEM>>>(
            As[l], btPtr + (size_t)l * KD * KD);
        if (l < 2)
            aggregate_kernel<<<NNODES, 128>>>(Bb[l], vdPtr + (l + 1) * KD * HEADS,
                                              (float*)0, 0);
        else
            aggregate_kernel<<<NNODES, 128>>>(Bb[l], vdPtr, out, 1);
    }
}

// round 11
// speedup vs baseline: 1.5887x; 1.0481x over previous
#include <cuda_runtime.h>
#include <cuda_bf16.h>
#include <cuda_fp16.h>
#include <math.h>
#include <stdint.h>

#define NNODES 50000
#define MPAD   50048      // 391 * 128
#define KD     256
#define HEADS  4
#define EMAX   1700000

// ---------------- device scratch --------------------------------------------
__device__ __half2         g_hsH[MPAD * KD / 2]; // source transform (fp16)
__device__ __half2         g_Af[MPAD * KD / 2];  // activations, plain fp16
__device__ __half          g_Bt[3 * KD * KD];    // W^T fp16, all layers
__device__ float           g_as[MPAD * HEADS];
__device__ float           g_ad[NNODES * HEADS];
__device__ float           g_vd[3 * KD * HEADS]; // Wd_l @ att_d_l, [l][k][h]
__device__ int             g_deg[NNODES];
__device__ int             g_rowptr[NNODES + 1];
__device__ int             g_cursor[NNODES];
__device__ int             g_srcs[EMAX];         // CSR-ordered SOURCE ids

// ---------------- helpers ----------------------------------------------------
__device__ __forceinline__ void mma_f16(float* c, const uint32_t* a, const uint32_t* b) {
    asm volatile(
        "mma.sync.aligned.m16n8k16.row.col.f32.f16.f16.f32 "
        "{%0,%1,%2,%3},{%4,%5,%6,%7},{%8,%9},{%0,%1,%2,%3};"
        : "+f"(c[0]), "+f"(c[1]), "+f"(c[2]), "+f"(c[3])
        : "r"(a[0]), "r"(a[1]), "r"(a[2]), "r"(a[3]), "r"(b[0]), "r"(b[1]));
}

#define CP_ASYNC16(dst_u32, src_ptr) \
    asm volatile("cp.async.cg.shared.global [%0], [%1], 16;" \
                 :: "r"(dst_u32), "l"(src_ptr))
#define CP_COMMIT() asm volatile("cp.async.commit_group;" ::: "memory")
#define CP_WAIT0()  asm volatile("cp.async.wait_group 0;" ::: "memory")

// ---------------- CSR build --------------------------------------------------
__global__ void count_deg_kernel(const int* __restrict__ dst, int e2) {
    int e = blockIdx.x * blockDim.x + threadIdx.x;
    if (e < e2) atomicAdd(&g_deg[dst[e]], 1);
}
__global__ void scan_kernel() {
    __shared__ int s[1024];
    int t = threadIdx.x;
    const int per = (NNODES + 1023) / 1024;
    int start = t * per;
    int end = start + per; if (end > NNODES) end = NNODES;
    int sum = 0;
    for (int i = start; i < end; i++) sum += g_deg[i];
    s[t] = sum;
    __syncthreads();
    for (int off = 1; off < 1024; off <<= 1) {
        int v = (t >= off) ? s[t - off] : 0;
        __syncthreads();
        s[t] += v;
        __syncthreads();
    }
    int run = (t > 0) ? s[t - 1] : 0;
    for (int i = start; i < end; i++) {
        int d = g_deg[i];
        g_rowptr[i] = run;
        g_cursor[i] = run;
        run += d;
    }
    if (t == 0) g_rowptr[NNODES] = s[1023];
}
__global__ void scatter_kernel(const int* __restrict__ src,
                               const int* __restrict__ dst, int e2) {
    int e = blockIdx.x * blockDim.x + threadIdx.x;
    if (e < e2) {
        int pos = atomicAdd(&g_cursor[dst[e]], 1);
        g_srcs[pos] = src[e];
    }
}

// ---------------- fused: x -> fp16 AND layer-0 a_d ---------------------------
__global__ void __launch_bounds__(256) prep_x_kernel(const float* __restrict__ X) {
    __shared__ float svd[KD * 4];
    int tid = threadIdx.x;
    for (int i = tid; i < KD * 4; i += 256) svd[i] = g_vd[i];
    __syncthreads();
    int warp = tid >> 5, lane = tid & 31;
    int n = blockIdx.x * 8 + warp;
    if (n >= NNODES) return;
    float a0 = 0.f, a1 = 0.f, a2 = 0.f, a3 = 0.f;
#pragma unroll
    for (int g4 = 0; g4 < 2; g4++) {
        int f4i = n * 64 + lane * 2 + g4;
        float4 xv = ((const float4*)X)[f4i];
        __half2 h01 = __floats2half2_rn(xv.x, xv.y);
        __half2 h23 = __floats2half2_rn(xv.z, xv.w);
        uint2 hp;
        hp.x = *reinterpret_cast<unsigned*>(&h01);
        hp.y = *reinterpret_cast<unsigned*>(&h23);
        ((uint2*)g_Af)[f4i] = hp;
        const float* p = &svd[(lane * 8 + g4 * 4) * 4];
        a0 += xv.x * p[0] + xv.y * p[4] + xv.z * p[8]  + xv.w * p[12];
        a1 += xv.x * p[1] + xv.y * p[5] + xv.z * p[9]  + xv.w * p[13];
        a2 += xv.x * p[2] + xv.y * p[6] + xv.z * p[10] + xv.w * p[14];
        a3 += xv.x * p[3] + xv.y * p[7] + xv.z * p[11] + xv.w * p[15];
    }
#pragma unroll
    for (int off = 16; off > 0; off >>= 1) {
        a0 += __shfl_xor_sync(0xffffffffu, a0, off);
        a1 += __shfl_xor_sync(0xffffffffu, a1, off);
        a2 += __shfl_xor_sync(0xffffffffu, a2, off);
        a3 += __shfl_xor_sync(0xffffffffu, a3, off);
    }
    if (lane == 0) ((float4*)g_ad)[n] = make_float4(a0, a1, a2, a3);
}

// ---------------- B transpose -> fp16, all 3 layers --------------------------
__global__ void btsplit_all_kernel(const float* __restrict__ W0,
                                   const float* __restrict__ W1,
                                   const float* __restrict__ W2) {
    int l = blockIdx.y;
    const float* W = (l == 0) ? W0 : (l == 1) ? W1 : W2;
    int i = blockIdx.x * blockDim.x + threadIdx.x;
    int n = i >> 8, k = i & 255;
    g_Bt[l * KD * KD + i] = __float2half_rn(W[k * KD + n]);
}

// ---------------- vd for all layers in one launch ----------------------------
__global__ void compute_vd_all_kernel(const float* __restrict__ Wd0,
                                      const float* __restrict__ Wd1,
                                      const float* __restrict__ Wd2,
                                      const float* __restrict__ ad0,
                                      const float* __restrict__ ad1,
                                      const float* __restrict__ ad2) {
    int l = blockIdx.x;
    const float* Wd = (l == 0) ? Wd0 : (l == 1) ? Wd1 : Wd2;
    const float* ad = (l == 0) ? ad0 : (l == 1) ? ad1 : ad2;
    int idx = threadIdx.x;
    int k = idx >> 2;
    int h = idx & 3;
    float s = 0.f;
#pragma unroll 8
    for (int c = 0; c < 64; c++) s += Wd[k * KD + h * 64 + c] * ad[h * 64 + c];
    g_vd[l * KD * HEADS + k * 4 + h] = s;
}

// ---------------- GEMM: hs(fp16) = A(fp16) @ B(fp16), single product ---------
#define S32 20
#define STAGE_W 5120
__global__ void __launch_bounds__(256) gemm_mma_kernel(const float* __restrict__ attS,
                                                       const __half* __restrict__ Bh) {
    extern __shared__ uint32_t smem_u[];
    __shared__ float s_as[128][2];
    const int tid = threadIdx.x;
    const int wid = tid >> 5, lane = tid & 31;
    const int wm = wid >> 2, wn = wid & 3;
    const int row0 = blockIdx.x * 128;
    const int n0 = blockIdx.y * 128;
    const int g8 = lane >> 2, tq = lane & 3;
    const uint32_t smem_b = (uint32_t)__cvta_generic_to_shared(smem_u);
    const __half* Af = (const __half*)g_Af;

    ((float*)s_as)[tid] = 0.f;

    const int lr0 = tid >> 2;
    const int lc4 = tid & 3;
    float c[4][4][4];
#pragma unroll
    for (int mt = 0; mt < 4; mt++)
#pragma unroll
        for (int nt = 0; nt < 4; nt++)
#pragma unroll
            for (int j = 0; j < 4; j++) c[mt][nt][j] = 0.f;

#define LOAD_CHUNK(stg, cc) do {                                               \
    int k0 = (cc) * 32;                                                        \
    _Pragma("unroll")                                                          \
    for (int i = 0; i < 2; i++) {                                              \
        int r = lr0 + i * 64;                                                  \
        long ga = (long)(row0 + r) * KD + k0 + lc4 * 8;                        \
        long gb = (long)(n0 + r) * KD + k0 + lc4 * 8;                          \
        uint32_t so = smem_b + ((stg) * STAGE_W + r * S32 + lc4 * 4) * 4;      \
        CP_ASYNC16(so,            Af + ga);                                    \
        CP_ASYNC16(so + 2560 * 4, Bh + gb);                                    \
    }                                                                          \
} while (0)

    LOAD_CHUNK(0, 0);
    CP_COMMIT();

    for (int cch = 0; cch < 8; cch++) {
        const int stg = cch & 1;
        CP_WAIT0();
        __syncthreads();
        if (cch < 7) { LOAD_CHUNK(stg ^ 1, cch + 1); CP_COMMIT(); }
        const uint32_t* sA  = smem_u + stg * STAGE_W;
        const uint32_t* sBh = sA + 2560;
#pragma unroll
        for (int kk = 0; kk < 2; kk++) {
            const int kb = kk * 8;
            uint32_t ah[4][4], bh[4][2];
#pragma unroll
            for (int mt = 0; mt < 4; mt++) {
                int r = (wm * 64 + mt * 16 + g8) * S32 + kb + tq;
                int r8 = r + 8 * S32;
                ah[mt][0] = sA[r];     ah[mt][1] = sA[r8];
                ah[mt][2] = sA[r + 4]; ah[mt][3] = sA[r8 + 4];
            }
#pragma unroll
            for (int nt = 0; nt < 4; nt++) {
                int r = (wn * 32 + nt * 8 + g8) * S32 + kb + tq;
                bh[nt][0] = sBh[r]; bh[nt][1] = sBh[r + 4];
            }
#pragma unroll
            for (int mt = 0; mt < 4; mt++)
#pragma unroll
                for (int nt = 0; nt < 4; nt++)
                    mma_f16(c[mt][nt], ah[mt], bh[nt]);
        }
        __syncthreads();
    }

    // epilogue 1: fragments -> g_hsH (fp16)
#pragma unroll
    for (int mt = 0; mt < 4; mt++) {
        int r = row0 + wm * 64 + mt * 16 + g8;
#pragma unroll
        for (int nt = 0; nt < 4; nt++) {
            int h2i = 64 * blockIdx.y + wn * 16 + nt * 4 + tq;
            g_hsH[(long)r * 128 + h2i]       = __floats2half2_rn(c[mt][nt][0], c[mt][nt][1]);
            g_hsH[(long)(r + 8) * 128 + h2i] = __floats2half2_rn(c[mt][nt][2], c[mt][nt][3]);
        }
    }
    // epilogue 2: fused a_s via block-shared reduction
    {
        float p0[4] = {0.f, 0.f, 0.f, 0.f};
        float p1[4] = {0.f, 0.f, 0.f, 0.f};
#pragma unroll
        for (int nt = 0; nt < 4; nt++) {
            int col = n0 + wn * 32 + nt * 8 + tq * 2;
            float a0 = attS[col], a1 = attS[col + 1];
#pragma unroll
            for (int mt = 0; mt < 4; mt++) {
                p0[mt] += c[mt][nt][0] * a0 + c[mt][nt][1] * a1;
                p1[mt] += c[mt][nt][2] * a0 + c[mt][nt][3] * a1;
            }
        }
        int hl = wn >> 1;
#pragma unroll
        for (int mt = 0; mt < 4; mt++) {
            p0[mt] += __shfl_xor_sync(0xffffffffu, p0[mt], 1);
            p0[mt] += __shfl_xor_sync(0xffffffffu, p0[mt], 2);
            p1[mt] += __shfl_xor_sync(0xffffffffu, p1[mt], 1);
            p1[mt] += __shfl_xor_sync(0xffffffffu, p1[mt], 2);
            if (tq == 0) {
                int rl = wm * 64 + mt * 16 + g8;
                atomicAdd(&s_as[rl][hl], p0[mt]);
                atomicAdd(&s_as[rl + 8][hl], p1[mt]);
            }
        }
        __syncthreads();
        int rl = tid >> 1, h2 = tid & 1;
        g_as[(row0 + rl) * 4 + blockIdx.y * 2 + h2] = s_as[rl][h2];
    }
}

// ---------------- aggregation: warp-per-edge LDG.128 gather ------------------
// Staging (threads 0..63) unchanged. Gather: warp w takes staged edges
// j ≡ w (mod 4); lane loads the full row's cols [8*lane, 8*lane+8) via uint4.
// Partials combined via shared; thread t then owns cols {2t, 2t+1} (same
// epilogue mapping as before).
__global__ void __launch_bounds__(128) aggregate_kernel(const float* __restrict__ bias,
                                                        const float* __restrict__ vdn,
                                                        float* __restrict__ out,
                                                        int mode) {
    __shared__ float s_ex[64][4];
    __shared__ int   s_si[64];
    __shared__ float sacc[4][256];
    __shared__ float sexs[4][4];
    __shared__ float s_adp[4][4];
    __shared__ float sh[256];
    __shared__ float s_red[2];

    const int n = blockIdx.x;
    const int tid = threadIdx.x;
    const int w = tid >> 5, lane = tid & 31;
    const int hsel = lane >> 3;           // head of this lane's 8 columns
    const int base = g_rowptr[n];
    const int deg = g_rowptr[n + 1] - base;

    float4 ad4 = make_float4(0.f, 0.f, 0.f, 0.f);
    if (tid < 64) ad4 = ((const float4*)g_ad)[n];

    const uint4* __restrict__ hs4u = (const uint4*)g_hsH;   // 32 uint4 per row

    float acc0 = 0.f, acc1 = 0.f, acc2 = 0.f, acc3 = 0.f;
    float acc4 = 0.f, acc5 = 0.f, acc6 = 0.f, acc7 = 0.f;
    float exs = 0.f;

#define EDGE_STEP(jj) do {                                        \
    float e = s_ex[jj][hsel];                                     \
    int s = s_si[jj];                                             \
    uint4 hv = hs4u[(long)s * 32 + lane];                         \
    float2 f0 = __half22float2(*(__half2*)&hv.x);                 \
    float2 f1 = __half22float2(*(__half2*)&hv.y);                 \
    float2 f2 = __half22float2(*(__half2*)&hv.z);                 \
    float2 f3 = __half22float2(*(__half2*)&hv.w);                 \
    acc0 += e * f0.x; acc1 += e * f0.y;                           \
    acc2 += e * f1.x; acc3 += e * f1.y;                           \
    acc4 += e * f2.x; acc5 += e * f2.y;                           \
    acc6 += e * f3.x; acc7 += e * f3.y;                           \
    exs += e;                                                     \
} while (0)

    for (int cs = 0; cs < deg; cs += 64) {
        int m = deg - cs; if (m > 64) m = 64;
        if (tid < m) {
            int sI = g_srcs[base + cs + tid];
            float4 a = ((const float4*)g_as)[sI];
            float v; float4 ex;
            v = a.x + ad4.x; v = v > 0.f ? v : 0.2f * v; ex.x = __expf(v);
            v = a.y + ad4.y; v = v > 0.f ? v : 0.2f * v; ex.y = __expf(v);
            v = a.z + ad4.z; v = v > 0.f ? v : 0.2f * v; ex.z = __expf(v);
            v = a.w + ad4.w; v = v > 0.f ? v : 0.2f * v; ex.w = __expf(v);
            *(float4*)s_ex[tid] = ex;
            s_si[tid] = sI;
        }
        __syncthreads();
        int j = w;
        for (; j + 12 < m; j += 16) {
            EDGE_STEP(j);
            EDGE_STEP(j + 4);
            EDGE_STEP(j + 8);
            EDGE_STEP(j + 12);
        }
        for (; j < m; j += 4) EDGE_STEP(j);
        __syncthreads();
    }

    // combine partials across warps
    *(float4*)&sacc[w][lane * 8]     = make_float4(acc0, acc1, acc2, acc3);
    *(float4*)&sacc[w][lane * 8 + 4] = make_float4(acc4, acc5, acc6, acc7);
    if ((lane & 7) == 0) sexs[w][hsel] = exs;
    __syncthreads();

    float v0 = sacc[0][tid * 2] + sacc[1][tid * 2] + sacc[2][tid * 2] + sacc[3][tid * 2];
    float v1 = sacc[0][tid * 2 + 1] + sacc[1][tid * 2 + 1]
             + sacc[2][tid * 2 + 1] + sacc[3][tid * 2 + 1];
    const float den = sexs[0][w] + sexs[1][w] + sexs[2][w] + sexs[3][w] + 1e-16f;
    v0 /= den;
    v1 /= den;

    const int col0 = tid * 2;            // = w*64 + lane*2 (same mapping as before)
    if (mode == 0) {
        v0 += bias[col0];
        v1 += bias[col0 + 1];
        v0 = v0 > 0.f ? v0 : expm1f(v0);
        v1 = v1 > 0.f ? v1 : expm1f(v1);
        g_Af[(long)n * 128 + tid] = __floats2half2_rn(v0, v1);
        const float* p0 = &vdn[col0 * 4];
        float q0 = v0 * p0[0] + v1 * p0[4];
        float q1 = v0 * p0[1] + v1 * p0[5];
        float q2 = v0 * p0[2] + v1 * p0[6];
        float q3 = v0 * p0[3] + v1 * p0[7];
#pragma unroll
        for (int off = 16; off > 0; off >>= 1) {
            q0 += __shfl_xor_sync(0xffffffffu, q0, off);
            q1 += __shfl_xor_sync(0xffffffffu, q1, off);
            q2 += __shfl_xor_sync(0xffffffffu, q2, off);
            q3 += __shfl_xor_sync(0xffffffffu, q3, off);
        }
        if (lane < 4) {
            float q = lane == 0 ? q0 : lane == 1 ? q1 : lane == 2 ? q2 : q3;
            s_adp[w][lane] = q;
        }
        __syncthreads();
        if (tid < 4)
            g_ad[n * 4 + tid] = s_adp[0][tid] + s_adp[1][tid] + s_adp[2][tid] + s_adp[3][tid];
    } else {
        sh[col0] = v0;
        sh[col0 + 1] = v1;
        __syncthreads();
        if (tid < 64)
            sh[tid] = 0.25f * (sh[tid] + sh[tid + 64] + sh[tid + 128] + sh[tid + 192]) + bias[tid];
        __syncthreads();
        if (tid < 32) {
            float a = fmaxf(sh[tid], sh[tid + 32]);
#pragma unroll
            for (int off = 16; off > 0; off >>= 1)
                a = fmaxf(a, __shfl_xor_sync(0xffffffffu, a, off));
            if (tid == 0) s_red[0] = a;
        }
        __syncthreads();
        if (tid < 32) {
            float mx = s_red[0];
            float a = expf(sh[tid] - mx) + expf(sh[tid + 32] - mx);
#pragma unroll
            for (int off = 16; off > 0; off >>= 1)
                a += __shfl_xor_sync(0xffffffffu, a, off);
            if (tid == 0) s_red[1] = a;
        }
        __syncthreads();
        if (tid < 64) out[(long)n * 64 + tid] = sh[tid] - s_red[0] - logf(s_red[1]);
    }
}

// ---------------- launch -----------------------------------------------------
extern "C" void kernel_launch(void* const* d_in, const int* in_sizes, int n_in,
                              void* d_out, int out_size) {
    const float* x = (const float*)d_in[0];
    const int* ei = (const int*)d_in[1];
    int e2 = in_sizes[1] / 2;
    const int* src = ei;
    const int* dstp = ei + e2;
    const float* Ws[3] = {(const float*)d_in[2], (const float*)d_in[7],  (const float*)d_in[12]};
    const float* Wd[3] = {(const float*)d_in[3], (const float*)d_in[8],  (const float*)d_in[13]};
    const float* As[3] = {(const float*)d_in[4], (const float*)d_in[9],  (const float*)d_in[14]};
    const float* Ad[3] = {(const float*)d_in[5], (const float*)d_in[10], (const float*)d_in[15]};
    const float* Bb[3] = {(const float*)d_in[6], (const float*)d_in[11], (const float*)d_in[16]};
    float* out = (float*)d_out;

    float* vdPtr = 0;      cudaGetSymbolAddress((void**)&vdPtr, g_vd);
    __half* btPtr = 0;     cudaGetSymbolAddress((void**)&btPtr, g_Bt);
    int* degPtr = 0;       cudaGetSymbolAddress((void**)&degPtr, g_deg);

    const int GEMM_SMEM = 2 * STAGE_W * 4;   // 40960 B
    cudaFuncSetAttribute(gemm_mma_kernel, cudaFuncAttributeMaxDynamicSharedMemorySize,
                         GEMM_SMEM);

    int gE = (e2 + 255) / 256;

    cudaMemsetAsync(degPtr, 0, NNODES * sizeof(int));
    count_deg_kernel<<<gE, 256>>>(dstp, e2);
    scan_kernel<<<1, 1024>>>();
    scatter_kernel<<<gE, 256>>>(src, dstp, e2);

    btsplit_all_kernel<<<dim3(KD * KD / 256, 3), 256>>>(Ws[0], Ws[1], Ws[2]);
    compute_vd_all_kernel<<<3, 1024>>>(Wd[0], Wd[1], Wd[2], Ad[0], Ad[1], Ad[2]);
    prep_x_kernel<<<(NNODES + 7) / 8, 256>>>(x);

    for (int l = 0; l < 3; l++) {
        gemm_mma_kernel<<<dim3(MPAD / 128, 2), 256, GEMM_SMEM>>>(
            As[l], btPtr + (size_t)l * KD * KD);
        if (l < 2)
            aggregate_kernel<<<NNODES, 128>>>(Bb[l], vdPtr + (l + 1) * KD * HEADS,
                                              (float*)0, 0);
        else
            aggregate_kernel<<<NNODES, 128>>>(Bb[l], vdPtr, out, 1);
    }
}

// round 12
// speedup vs baseline: 1.7979x; 1.1317x over previous
#include <cuda_runtime.h>
#include <cuda_bf16.h>
#include <cuda_fp16.h>
#include <math.h>
#include <stdint.h>

#define NNODES 50000
#define MPAD   50048      // 391 * 128
#define KD     256
#define HEADS  4
#define EMAX   1700000

// ---------------- device scratch --------------------------------------------
__device__ __half2         g_hsH[MPAD * KD / 2]; // source transform (fp16)
__device__ __half2         g_Af[MPAD * KD / 2];  // activations, plain fp16
__device__ __half          g_Bt[3 * KD * KD];    // W^T fp16, all layers
__device__ float           g_as[MPAD * HEADS];
__device__ float           g_ad[NNODES * HEADS];
__device__ float           g_vd[3 * KD * HEADS]; // Wd_l @ att_d_l, [l][k][h]
__device__ int             g_deg[NNODES];
__device__ int             g_rowptr[NNODES + 1];
__device__ int             g_cursor[NNODES];
__device__ int             g_srcs[EMAX];         // CSR-ordered SOURCE ids

// ---------------- helpers ----------------------------------------------------
__device__ __forceinline__ void mma_f16(float* c, const uint32_t* a, const uint32_t* b) {
    asm volatile(
        "mma.sync.aligned.m16n8k16.row.col.f32.f16.f16.f32 "
        "{%0,%1,%2,%3},{%4,%5,%6,%7},{%8,%9},{%0,%1,%2,%3};"
        : "+f"(c[0]), "+f"(c[1]), "+f"(c[2]), "+f"(c[3])
        : "r"(a[0]), "r"(a[1]), "r"(a[2]), "r"(a[3]), "r"(b[0]), "r"(b[1]));
}

#define CP_ASYNC16(dst_u32, src_ptr) \
    asm volatile("cp.async.cg.shared.global [%0], [%1], 16;" \
                 :: "r"(dst_u32), "l"(src_ptr))
#define CP_COMMIT() asm volatile("cp.async.commit_group;" ::: "memory")
#define CP_WAIT0()  asm volatile("cp.async.wait_group 0;" ::: "memory")

// ---------------- CSR build --------------------------------------------------
__global__ void count_deg_kernel(const int* __restrict__ dst, int e2) {
    int e = blockIdx.x * blockDim.x + threadIdx.x;
    if (e < e2) atomicAdd(&g_deg[dst[e]], 1);
}
__global__ void scan_kernel() {
    __shared__ int s[1024];
    int t = threadIdx.x;
    const int per = (NNODES + 1023) / 1024;
    int start = t * per;
    int end = start + per; if (end > NNODES) end = NNODES;
    int sum = 0;
    for (int i = start; i < end; i++) sum += g_deg[i];
    s[t] = sum;
    __syncthreads();
    for (int off = 1; off < 1024; off <<= 1) {
        int v = (t >= off) ? s[t - off] : 0;
        __syncthreads();
        s[t] += v;
        __syncthreads();
    }
    int run = (t > 0) ? s[t - 1] : 0;
    for (int i = start; i < end; i++) {
        int d = g_deg[i];
        g_rowptr[i] = run;
        g_cursor[i] = run;
        run += d;
    }
    if (t == 0) g_rowptr[NNODES] = s[1023];
}
__global__ void scatter_kernel(const int* __restrict__ src,
                               const int* __restrict__ dst, int e2) {
    int e = blockIdx.x * blockDim.x + threadIdx.x;
    if (e < e2) {
        int pos = atomicAdd(&g_cursor[dst[e]], 1);
        g_srcs[pos] = src[e];
    }
}

// ---------------- fused: x -> fp16 AND layer-0 a_d ---------------------------
__global__ void __launch_bounds__(256) prep_x_kernel(const float* __restrict__ X) {
    __shared__ float svd[KD * 4];
    int tid = threadIdx.x;
    for (int i = tid; i < KD * 4; i += 256) svd[i] = g_vd[i];
    __syncthreads();
    int warp = tid >> 5, lane = tid & 31;
    int n = blockIdx.x * 8 + warp;
    if (n >= NNODES) return;
    float a0 = 0.f, a1 = 0.f, a2 = 0.f, a3 = 0.f;
#pragma unroll
    for (int g4 = 0; g4 < 2; g4++) {
        int f4i = n * 64 + lane * 2 + g4;
        float4 xv = ((const float4*)X)[f4i];
        __half2 h01 = __floats2half2_rn(xv.x, xv.y);
        __half2 h23 = __floats2half2_rn(xv.z, xv.w);
        uint2 hp;
        hp.x = *reinterpret_cast<unsigned*>(&h01);
        hp.y = *reinterpret_cast<unsigned*>(&h23);
        ((uint2*)g_Af)[f4i] = hp;
        const float* p = &svd[(lane * 8 + g4 * 4) * 4];
        a0 += xv.x * p[0] + xv.y * p[4] + xv.z * p[8]  + xv.w * p[12];
        a1 += xv.x * p[1] + xv.y * p[5] + xv.z * p[9]  + xv.w * p[13];
        a2 += xv.x * p[2] + xv.y * p[6] + xv.z * p[10] + xv.w * p[14];
        a3 += xv.x * p[3] + xv.y * p[7] + xv.z * p[11] + xv.w * p[15];
    }
#pragma unroll
    for (int off = 16; off > 0; off >>= 1) {
        a0 += __shfl_xor_sync(0xffffffffu, a0, off);
        a1 += __shfl_xor_sync(0xffffffffu, a1, off);
        a2 += __shfl_xor_sync(0xffffffffu, a2, off);
        a3 += __shfl_xor_sync(0xffffffffu, a3, off);
    }
    if (lane == 0) ((float4*)g_ad)[n] = make_float4(a0, a1, a2, a3);
}

// ---------------- B transpose -> fp16, all 3 layers --------------------------
__global__ void btsplit_all_kernel(const float* __restrict__ W0,
                                   const float* __restrict__ W1,
                                   const float* __restrict__ W2) {
    int l = blockIdx.y;
    const float* W = (l == 0) ? W0 : (l == 1) ? W1 : W2;
    int i = blockIdx.x * blockDim.x + threadIdx.x;
    int n = i >> 8, k = i & 255;
    g_Bt[l * KD * KD + i] = __float2half_rn(W[k * KD + n]);
}

// ---------------- vd for all layers in one launch ----------------------------
__global__ void compute_vd_all_kernel(const float* __restrict__ Wd0,
                                      const float* __restrict__ Wd1,
                                      const float* __restrict__ Wd2,
                                      const float* __restrict__ ad0,
                                      const float* __restrict__ ad1,
                                      const float* __restrict__ ad2) {
    int l = blockIdx.x;
    const float* Wd = (l == 0) ? Wd0 : (l == 1) ? Wd1 : Wd2;
    const float* ad = (l == 0) ? ad0 : (l == 1) ? ad1 : ad2;
    int idx = threadIdx.x;
    int k = idx >> 2;
    int h = idx & 3;
    float s = 0.f;
#pragma unroll 8
    for (int c = 0; c < 64; c++) s += Wd[k * KD + h * 64 + c] * ad[h * 64 + c];
    g_vd[l * KD * HEADS + k * 4 + h] = s;
}

// ---------------- GEMM: hs(fp16) = A(fp16) @ B(fp16), single product ---------
#define S32 20
#define STAGE_W 5120
__global__ void __launch_bounds__(256) gemm_mma_kernel(const float* __restrict__ attS,
                                                       const __half* __restrict__ Bh) {
    extern __shared__ uint32_t smem_u[];
    __shared__ float s_as[128][2];
    const int tid = threadIdx.x;
    const int wid = tid >> 5, lane = tid & 31;
    const int wm = wid >> 2, wn = wid & 3;
    const int row0 = blockIdx.x * 128;
    const int n0 = blockIdx.y * 128;
    const int g8 = lane >> 2, tq = lane & 3;
    const uint32_t smem_b = (uint32_t)__cvta_generic_to_shared(smem_u);
    const __half* Af = (const __half*)g_Af;

    ((float*)s_as)[tid] = 0.f;

    const int lr0 = tid >> 2;
    const int lc4 = tid & 3;
    float c[4][4][4];
#pragma unroll
    for (int mt = 0; mt < 4; mt++)
#pragma unroll
        for (int nt = 0; nt < 4; nt++)
#pragma unroll
            for (int j = 0; j < 4; j++) c[mt][nt][j] = 0.f;

#define LOAD_CHUNK(stg, cc) do {                                               \
    int k0 = (cc) * 32;                                                        \
    _Pragma("unroll")                                                          \
    for (int i = 0; i < 2; i++) {                                              \
        int r = lr0 + i * 64;                                                  \
        long ga = (long)(row0 + r) * KD + k0 + lc4 * 8;                        \
        long gb = (long)(n0 + r) * KD + k0 + lc4 * 8;                          \
        uint32_t so = smem_b + ((stg) * STAGE_W + r * S32 + lc4 * 4) * 4;      \
        CP_ASYNC16(so,            Af + ga);                                    \
        CP_ASYNC16(so + 2560 * 4, Bh + gb);                                    \
    }                                                                          \
} while (0)

    LOAD_CHUNK(0, 0);
    CP_COMMIT();

    for (int cch = 0; cch < 8; cch++) {
        const int stg = cch & 1;
        CP_WAIT0();
        __syncthreads();
        if (cch < 7) { LOAD_CHUNK(stg ^ 1, cch + 1); CP_COMMIT(); }
        const uint32_t* sA  = smem_u + stg * STAGE_W;
        const uint32_t* sBh = sA + 2560;
#pragma unroll
        for (int kk = 0; kk < 2; kk++) {
            const int kb = kk * 8;
            uint32_t ah[4][4], bh[4][2];
#pragma unroll
            for (int mt = 0; mt < 4; mt++) {
                int r = (wm * 64 + mt * 16 + g8) * S32 + kb + tq;
                int r8 = r + 8 * S32;
                ah[mt][0] = sA[r];     ah[mt][1] = sA[r8];
                ah[mt][2] = sA[r + 4]; ah[mt][3] = sA[r8 + 4];
            }
#pragma unroll
            for (int nt = 0; nt < 4; nt++) {
                int r = (wn * 32 + nt * 8 + g8) * S32 + kb + tq;
                bh[nt][0] = sBh[r]; bh[nt][1] = sBh[r + 4];
            }
#pragma unroll
            for (int mt = 0; mt < 4; mt++)
#pragma unroll
                for (int nt = 0; nt < 4; nt++)
                    mma_f16(c[mt][nt], ah[mt], bh[nt]);
        }
        __syncthreads();
    }

    // epilogue 1: fragments -> g_hsH (fp16)
#pragma unroll
    for (int mt = 0; mt < 4; mt++) {
        int r = row0 + wm * 64 + mt * 16 + g8;
#pragma unroll
        for (int nt = 0; nt < 4; nt++) {
            int h2i = 64 * blockIdx.y + wn * 16 + nt * 4 + tq;
            g_hsH[(long)r * 128 + h2i]       = __floats2half2_rn(c[mt][nt][0], c[mt][nt][1]);
            g_hsH[(long)(r + 8) * 128 + h2i] = __floats2half2_rn(c[mt][nt][2], c[mt][nt][3]);
        }
    }
    // epilogue 2: fused a_s via block-shared reduction
    {
        float p0[4] = {0.f, 0.f, 0.f, 0.f};
        float p1[4] = {0.f, 0.f, 0.f, 0.f};
#pragma unroll
        for (int nt = 0; nt < 4; nt++) {
            int col = n0 + wn * 32 + nt * 8 + tq * 2;
            float a0 = attS[col], a1 = attS[col + 1];
#pragma unroll
            for (int mt = 0; mt < 4; mt++) {
                p0[mt] += c[mt][nt][0] * a0 + c[mt][nt][1] * a1;
                p1[mt] += c[mt][nt][2] * a0 + c[mt][nt][3] * a1;
            }
        }
        int hl = wn >> 1;
#pragma unroll
        for (int mt = 0; mt < 4; mt++) {
            p0[mt] += __shfl_xor_sync(0xffffffffu, p0[mt], 1);
            p0[mt] += __shfl_xor_sync(0xffffffffu, p0[mt], 2);
            p1[mt] += __shfl_xor_sync(0xffffffffu, p1[mt], 1);
            p1[mt] += __shfl_xor_sync(0xffffffffu, p1[mt], 2);
            if (tq == 0) {
                int rl = wm * 64 + mt * 16 + g8;
                atomicAdd(&s_as[rl][hl], p0[mt]);
                atomicAdd(&s_as[rl + 8][hl], p1[mt]);
            }
        }
        __syncthreads();
        int rl = tid >> 1, h2 = tid & 1;
        g_as[(row0 + rl) * 4 + blockIdx.y * 2 + h2] = s_as[rl][h2];
    }
}

// ---------------- aggregation: warp-per-edge LDG.128 gather ------------------
__global__ void __launch_bounds__(128) aggregate_kernel(const float* __restrict__ bias,
                                                        const float* __restrict__ vdn,
                                                        float* __restrict__ out,
                                                        int mode) {
    __shared__ float s_ex[64][4];
    __shared__ int   s_si[64];
    __shared__ float sacc[4][256];
    __shared__ float sexs[4][4];
    __shared__ float s_adp[4][4];
    __shared__ float sh[256];
    __shared__ float s_red[2];

    const int n = blockIdx.x;
    const int tid = threadIdx.x;
    const int w = tid >> 5, lane = tid & 31;
    const int hsel = lane >> 3;
    const int base = g_rowptr[n];
    const int deg = g_rowptr[n + 1] - base;

    float4 ad4 = make_float4(0.f, 0.f, 0.f, 0.f);
    if (tid < 64) ad4 = ((const float4*)g_ad)[n];

    const uint4* __restrict__ hs4u = (const uint4*)g_hsH;

    float acc0 = 0.f, acc1 = 0.f, acc2 = 0.f, acc3 = 0.f;
    float acc4 = 0.f, acc5 = 0.f, acc6 = 0.f, acc7 = 0.f;
    float exs = 0.f;

#define EDGE_STEP(jj) do {                                        \
    float e = s_ex[jj][hsel];                                     \
    int s = s_si[jj];                                             \
    uint4 hv = hs4u[(long)s * 32 + lane];                         \
    float2 f0 = __half22float2(*(__half2*)&hv.x);                 \
    float2 f1 = __half22float2(*(__half2*)&hv.y);                 \
    float2 f2 = __half22float2(*(__half2*)&hv.z);                 \
    float2 f3 = __half22float2(*(__half2*)&hv.w);                 \
    acc0 += e * f0.x; acc1 += e * f0.y;                           \
    acc2 += e * f1.x; acc3 += e * f1.y;                           \
    acc4 += e * f2.x; acc5 += e * f2.y;                           \
    acc6 += e * f3.x; acc7 += e * f3.y;                           \
    exs += e;                                                     \
} while (0)

    for (int cs = 0; cs < deg; cs += 64) {
        int m = deg - cs; if (m > 64) m = 64;
        if (tid < m) {
            int sI = g_srcs[base + cs + tid];
            float4 a = ((const float4*)g_as)[sI];
            float v; float4 ex;
            v = a.x + ad4.x; v = v > 0.f ? v : 0.2f * v; ex.x = __expf(v);
            v = a.y + ad4.y; v = v > 0.f ? v : 0.2f * v; ex.y = __expf(v);
            v = a.z + ad4.z; v = v > 0.f ? v : 0.2f * v; ex.z = __expf(v);
            v = a.w + ad4.w; v = v > 0.f ? v : 0.2f * v; ex.w = __expf(v);
            *(float4*)s_ex[tid] = ex;
            s_si[tid] = sI;
        }
        __syncthreads();
        int j = w;
        for (; j + 12 < m; j += 16) {
            EDGE_STEP(j);
            EDGE_STEP(j + 4);
            EDGE_STEP(j + 8);
            EDGE_STEP(j + 12);
        }
        for (; j < m; j += 4) EDGE_STEP(j);
        __syncthreads();
    }

    *(float4*)&sacc[w][lane * 8]     = make_float4(acc0, acc1, acc2, acc3);
    *(float4*)&sacc[w][lane * 8 + 4] = make_float4(acc4, acc5, acc6, acc7);
    if ((lane & 7) == 0) sexs[w][hsel] = exs;
    __syncthreads();

    float v0 = sacc[0][tid * 2] + sacc[1][tid * 2] + sacc[2][tid * 2] + sacc[3][tid * 2];
    float v1 = sacc[0][tid * 2 + 1] + sacc[1][tid * 2 + 1]
             + sacc[2][tid * 2 + 1] + sacc[3][tid * 2 + 1];
    const float den = sexs[0][w] + sexs[1][w] + sexs[2][w] + sexs[3][w] + 1e-16f;
    v0 /= den;
    v1 /= den;

    const int col0 = tid * 2;
    if (mode == 0) {
        v0 += bias[col0];
        v1 += bias[col0 + 1];
        v0 = v0 > 0.f ? v0 : expm1f(v0);
        v1 = v1 > 0.f ? v1 : expm1f(v1);
        g_Af[(long)n * 128 + tid] = __floats2half2_rn(v0, v1);
        const float* p0 = &vdn[col0 * 4];
        float q0 = v0 * p0[0] + v1 * p0[4];
        float q1 = v0 * p0[1] + v1 * p0[5];
        float q2 = v0 * p0[2] + v1 * p0[6];
        float q3 = v0 * p0[3] + v1 * p0[7];
#pragma unroll
        for (int off = 16; off > 0; off >>= 1) {
            q0 += __shfl_xor_sync(0xffffffffu, q0, off);
            q1 += __shfl_xor_sync(0xffffffffu, q1, off);
            q2 += __shfl_xor_sync(0xffffffffu, q2, off);
            q3 += __shfl_xor_sync(0xffffffffu, q3, off);
        }
        if (lane < 4) {
            float q = lane == 0 ? q0 : lane == 1 ? q1 : lane == 2 ? q2 : q3;
            s_adp[w][lane] = q;
        }
        __syncthreads();
        if (tid < 4)
            g_ad[n * 4 + tid] = s_adp[0][tid] + s_adp[1][tid] + s_adp[2][tid] + s_adp[3][tid];
    } else {
        sh[col0] = v0;
        sh[col0 + 1] = v1;
        __syncthreads();
        if (tid < 64)
            sh[tid] = 0.25f * (sh[tid] + sh[tid + 64] + sh[tid + 128] + sh[tid + 192]) + bias[tid];
        __syncthreads();
        if (tid < 32) {
            float a = fmaxf(sh[tid], sh[tid + 32]);
#pragma unroll
            for (int off = 16; off > 0; off >>= 1)
                a = fmaxf(a, __shfl_xor_sync(0xffffffffu, a, off));
            if (tid == 0) s_red[0] = a;
        }
        __syncthreads();
        if (tid < 32) {
            float mx = s_red[0];
            float a = expf(sh[tid] - mx) + expf(sh[tid + 32] - mx);
#pragma unroll
            for (int off = 16; off > 0; off >>= 1)
                a += __shfl_xor_sync(0xffffffffu, a, off);
            if (tid == 0) s_red[1] = a;
        }
        __syncthreads();
        if (tid < 64) out[(long)n * 64 + tid] = sh[tid] - s_red[0] - logf(s_red[1]);
    }
}

// ---------------- launch: CSR forked onto a side stream ----------------------
extern "C" void kernel_launch(void* const* d_in, const int* in_sizes, int n_in,
                              void* d_out, int out_size) {
    const float* x = (const float*)d_in[0];
    const int* ei = (const int*)d_in[1];
    int e2 = in_sizes[1] / 2;
    const int* src = ei;
    const int* dstp = ei + e2;
    const float* Ws[3] = {(const float*)d_in[2], (const float*)d_in[7],  (const float*)d_in[12]};
    const float* Wd[3] = {(const float*)d_in[3], (const float*)d_in[8],  (const float*)d_in[13]};
    const float* As[3] = {(const float*)d_in[4], (const float*)d_in[9],  (const float*)d_in[14]};
    const float* Ad[3] = {(const float*)d_in[5], (const float*)d_in[10], (const float*)d_in[15]};
    const float* Bb[3] = {(const float*)d_in[6], (const float*)d_in[11], (const float*)d_in[16]};
    float* out = (float*)d_out;

    float* vdPtr = 0;      cudaGetSymbolAddress((void**)&vdPtr, g_vd);
    __half* btPtr = 0;     cudaGetSymbolAddress((void**)&btPtr, g_Bt);
    int* degPtr = 0;       cudaGetSymbolAddress((void**)&degPtr, g_deg);

    const int GEMM_SMEM = 2 * STAGE_W * 4;   // 40960 B
    cudaFuncSetAttribute(gemm_mma_kernel, cudaFuncAttributeMaxDynamicSharedMemorySize,
                         GEMM_SMEM);

    int gE = (e2 + 255) / 256;

    // Fork a side stream for the CSR chain (independent of prologue + gemm0).
    cudaStream_t s2;
    cudaStreamCreateWithFlags(&s2, cudaStreamNonBlocking);
    cudaEvent_t eFork, eJoin;
    cudaEventCreateWithFlags(&eFork, cudaEventDisableTiming);
    cudaEventCreateWithFlags(&eJoin, cudaEventDisableTiming);

    cudaEventRecord(eFork, 0);
    cudaStreamWaitEvent(s2, eFork, 0);

    // side stream: CSR build
    cudaMemsetAsync(degPtr, 0, NNODES * sizeof(int), s2);
    count_deg_kernel<<<gE, 256, 0, s2>>>(dstp, e2);
    scan_kernel<<<1, 1024, 0, s2>>>();
    scatter_kernel<<<gE, 256, 0, s2>>>(src, dstp, e2);
    cudaEventRecord(eJoin, s2);

    // main stream: prologue + layer-0 GEMM (no CSR dependence)
    btsplit_all_kernel<<<dim3(KD * KD / 256, 3), 256>>>(Ws[0], Ws[1], Ws[2]);
    compute_vd_all_kernel<<<3, 1024>>>(Wd[0], Wd[1], Wd[2], Ad[0], Ad[1], Ad[2]);
    prep_x_kernel<<<(NNODES + 7) / 8, 256>>>(x);
    gemm_mma_kernel<<<dim3(MPAD / 128, 2), 256, GEMM_SMEM>>>(As[0], btPtr);

    // join: aggregate needs the CSR
    cudaStreamWaitEvent(0, eJoin, 0);

    aggregate_kernel<<<NNODES, 128>>>(Bb[0], vdPtr + 1 * KD * HEADS, (float*)0, 0);
    for (int l = 1; l < 3; l++) {
        gemm_mma_kernel<<<dim3(MPAD / 128, 2), 256, GEMM_SMEM>>>(
            As[l], btPtr + (size_t)l * KD * KD);
        if (l < 2)
            aggregate_kernel<<<NNODES, 128>>>(Bb[l], vdPtr + (l + 1) * KD * HEADS,
                                              (float*)0, 0);
        else
            aggregate_kernel<<<NNODES, 128>>>(Bb[l], vdPtr, out, 1);
    }
    // Intentionally not destroying s2/eFork/eJoin here: destruction while the
    // surrounding graph capture is still active invalidates the capture. The
    // handles are tiny host-side objects (~2 calls total, no device memory).
}